// round 1
// baseline (speedup 1.0000x reference)
#include <cuda_runtime.h>
#include <mma.h>
#include <cstdint>
#include <cmath>

using namespace nvcuda;

#define NTOK   262152
#define CDIM   256
#define NSETS  7282
#define SETSZ  36
#define NHEAD  8
#define DHEAD  32
#define DFFN   1024

// ---------------------------------------------------------------------------
// Scratch (device globals -- no allocations allowed)
// ---------------------------------------------------------------------------
__device__ float g_x   [(size_t)NTOK * CDIM];
__device__ float g_res [(size_t)NTOK * CDIM];
__device__ float g_qk  [(size_t)NTOK * CDIM];
__device__ float g_feat[(size_t)NTOK * CDIM];
__device__ float g_qkp [(size_t)NTOK * 512];
__device__ float g_v   [(size_t)NTOK * CDIM];
__device__ float g_attn[(size_t)NTOK * CDIM];
__device__ float g_o   [(size_t)NTOK * CDIM];
__device__ float g_x1  [(size_t)NTOK * CDIM];
__device__ float g_h   [(size_t)NTOK * DFFN];
__device__ float g_ff  [(size_t)NTOK * CDIM];
__device__ int   g_mask_mode;   // 0=int32, 1=uint8/bool, 2=float32

// ---------------------------------------------------------------------------
// Mask dtype detector: scans the mask buffer's first 1MB as 32-bit words.
//   int32 storage  -> words are only 0 or 1
//   float32 storage-> words are only 0 or 0x3F800000
//   uint8/bool     -> words with bytes set outside byte 0 appear (20% density)
// Deterministic for fixed input.
// ---------------------------------------------------------------------------
__global__ void detect_mask_kernel(const unsigned int* __restrict__ w, int nwords)
{
    __shared__ int f32f, u8f;
    if (threadIdx.x == 0) { f32f = 0; u8f = 0; }
    __syncthreads();
    int lf = 0, lu = 0;
    for (int i = threadIdx.x; i < nwords; i += blockDim.x) {
        unsigned int x = w[i];
        if (x == 0x3F800000u) lf = 1;
        else if (x > 1u)      lu = 1;
    }
    if (lf) f32f = 1;
    if (lu) u8f = 1;
    __syncthreads();
    if (threadIdx.x == 0) g_mask_mode = f32f ? 2 : (u8f ? 1 : 0);
}

// ---------------------------------------------------------------------------
// Gather: qk[j] = x[inds[j]] + pos[inds[j]]; feat[j] = x[inds[j]]
// ---------------------------------------------------------------------------
__global__ __launch_bounds__(256) void gather_kernel(
    const float* __restrict__ x, const float* __restrict__ pos,
    const int* __restrict__ inds, float* __restrict__ qk,
    float* __restrict__ feat)
{
    int idx = blockIdx.x * 256 + threadIdx.x;
    if (idx >= NTOK * 64) return;
    int j  = idx >> 6;
    int c4 = idx & 63;
    int t  = inds[j];
    float4 xv = ((const float4*)x)  [(size_t)t * 64 + c4];
    float4 pv = ((const float4*)pos)[(size_t)t * 64 + c4];
    ((float4*)feat)[(size_t)j * 64 + c4] = xv;
    ((float4*)qk)  [(size_t)j * 64 + c4] =
        make_float4(xv.x + pv.x, xv.y + pv.y, xv.z + pv.z, xv.w + pv.w);
}

// ---------------------------------------------------------------------------
// GEMM: C[m,n] = sum_k A[m,k] * W[n,k] + bias[n]  (+ optional exact GELU)
// 3xTF32 error-compensated wmma (fp32-equivalent accuracy, tensor-core rate).
// CTA tile 128x128, BK=32, 8 warps each computing 64x32 (4x2 m16n16k8 frags).
// ---------------------------------------------------------------------------
#define BM 128
#define BN 128
#define BK 32

__global__ __launch_bounds__(256, 1) void gemm_tf32x3_kernel(
    const float* __restrict__ A, const float* __restrict__ W,
    const float* __restrict__ bias, float* __restrict__ C,
    int M, int N, int K, int act)
{
    __shared__ float As[BM][BK + 4];
    __shared__ float Bs[BN][BK + 4];
    __shared__ float Ep[8][256];

    const int tid  = threadIdx.x;
    const int warp = tid >> 5;
    const int lane = tid & 31;
    const int wr   = warp >> 2;   // 0..1
    const int wc   = warp & 3;    // 0..3
    const int m0   = blockIdx.x * BM;
    const int n0   = blockIdx.y * BN;

    wmma::fragment<wmma::accumulator, 16, 16, 8, float> acc[4][2];
#pragma unroll
    for (int i = 0; i < 4; i++)
#pragma unroll
        for (int j = 0; j < 2; j++)
            wmma::fill_fragment(acc[i][j], 0.0f);

    for (int k0 = 0; k0 < K; k0 += BK) {
        // stage A(128x32) and W(128x32) tiles; 4 float4s per thread each
#pragma unroll
        for (int it = 0; it < 4; it++) {
            int li = tid + it * 256;
            int r  = li >> 3;
            int c4 = (li & 7) << 2;
            float4 va = make_float4(0.f, 0.f, 0.f, 0.f);
            int gr = m0 + r;
            if (gr < M) va = *(const float4*)(A + (size_t)gr * K + k0 + c4);
            *(float4*)(&As[r][c4]) = va;
            float4 vb = make_float4(0.f, 0.f, 0.f, 0.f);
            int gn = n0 + r;
            if (gn < N) vb = *(const float4*)(W + (size_t)gn * K + k0 + c4);
            *(float4*)(&Bs[r][c4]) = vb;
        }
        __syncthreads();
#pragma unroll
        for (int kk = 0; kk < BK; kk += 8) {
            wmma::fragment<wmma::matrix_a, 16, 16, 8, wmma::precision::tf32,
                           wmma::row_major> ah[4], al[4];
            wmma::fragment<wmma::matrix_b, 16, 16, 8, wmma::precision::tf32,
                           wmma::col_major> bh[2], bl[2];
#pragma unroll
            for (int i = 0; i < 4; i++) {
                wmma::load_matrix_sync(ah[i], &As[wr * 64 + i * 16][kk], BK + 4);
#pragma unroll
                for (int t = 0; t < ah[i].num_elements; t++) {
                    float f  = ah[i].x[t];
                    float hi = wmma::__float_to_tf32(f);
                    ah[i].x[t] = hi;
                    al[i].x[t] = wmma::__float_to_tf32(f - hi);
                }
            }
#pragma unroll
            for (int j = 0; j < 2; j++) {
                wmma::load_matrix_sync(bh[j], &Bs[wc * 32 + j * 16][kk], BK + 4);
#pragma unroll
                for (int t = 0; t < bh[j].num_elements; t++) {
                    float f  = bh[j].x[t];
                    float hi = wmma::__float_to_tf32(f);
                    bh[j].x[t] = hi;
                    bl[j].x[t] = wmma::__float_to_tf32(f - hi);
                }
            }
#pragma unroll
            for (int i = 0; i < 4; i++)
#pragma unroll
                for (int j = 0; j < 2; j++) {
                    wmma::mma_sync(acc[i][j], al[i], bh[j], acc[i][j]);
                    wmma::mma_sync(acc[i][j], ah[i], bl[j], acc[i][j]);
                    wmma::mma_sync(acc[i][j], ah[i], bh[j], acc[i][j]);
                }
        }
        __syncthreads();
    }

    // epilogue: stage each 16x16 frag through smem for guarded, fused writes
#pragma unroll
    for (int i = 0; i < 4; i++)
#pragma unroll
        for (int j = 0; j < 2; j++) {
            wmma::store_matrix_sync(&Ep[warp][0], acc[i][j], 16, wmma::mem_row_major);
            __syncwarp();
#pragma unroll
            for (int e = 0; e < 8; e++) {
                int idx = lane + e * 32;
                int rr = idx >> 4, cc = idx & 15;
                int gr = m0 + wr * 64 + i * 16 + rr;
                int gc = n0 + wc * 32 + j * 16 + cc;
                if (gr < M && gc < N) {
                    float v = Ep[warp][idx] + bias[gc];
                    if (act) v = 0.5f * v * (1.0f + erff(v * 0.70710678118654752f));
                    C[(size_t)gr * N + gc] = v;
                }
            }
            __syncwarp();
        }
}

// ---------------------------------------------------------------------------
// Set attention: one block per (set, 4-head group). 144 threads = 4 heads x 36
// query rows. K,V in smem; q row, scores, output row in registers. fp32 exact.
// ---------------------------------------------------------------------------
__global__ __launch_bounds__(144, 1) void attn_kernel(
    const float* __restrict__ qkp, const float* __restrict__ vb,
    const void* __restrict__ maskp, int mask_off,
    float* __restrict__ outp)
{
    const int s   = blockIdx.x;
    const int h0  = blockIdx.y * 4;
    const int tid = threadIdx.x;
    const int hl  = tid / SETSZ;
    const int l   = tid - hl * SETSZ;

    __shared__ float ks[4][SETSZ][DHEAD];
    __shared__ float vs[4][SETSZ][DHEAD];
    __shared__ float msk[SETSZ];

    if (tid < SETSZ) {
        int gi = mask_off + s * SETSZ + tid;
        int mode = g_mask_mode;
        bool m;
        if (mode == 0)      m = ((const int*)maskp)[gi] != 0;
        else if (mode == 1) m = ((const unsigned char*)maskp)[gi] != 0;
        else                m = ((const float*)maskp)[gi] != 0.0f;
        msk[tid] = m ? -INFINITY : 0.0f;
    }
    for (int idx = tid; idx < 4 * SETSZ * DHEAD; idx += 144) {
        int d  = idx & (DHEAD - 1);
        int m  = (idx >> 5) % SETSZ;
        int hh = idx / (DHEAD * SETSZ);
        size_t row = (size_t)s * SETSZ + m;
        ks[hh][m][d] = qkp[row * 512 + 256 + (size_t)(h0 + hh) * DHEAD + d];
        vs[hh][m][d] = vb [row * 256 +       (size_t)(h0 + hh) * DHEAD + d];
    }
    __syncthreads();

    float q[DHEAD];
    {
        const float4* qr = (const float4*)(qkp + ((size_t)s * SETSZ + l) * 512
                                           + (size_t)(h0 + hl) * DHEAD);
#pragma unroll
        for (int d4 = 0; d4 < 8; d4++) {
            float4 vq = qr[d4];
            q[d4*4+0] = vq.x; q[d4*4+1] = vq.y; q[d4*4+2] = vq.z; q[d4*4+3] = vq.w;
        }
    }
    const float scale = 0.17677669529663687f;  // 1/sqrt(32)
    float sc[SETSZ];
    float mx = -INFINITY;
#pragma unroll
    for (int m = 0; m < SETSZ; m++) {
        float a = 0.f;
#pragma unroll
        for (int d = 0; d < DHEAD; d++) a += q[d] * ks[hl][m][d];
        a = a * scale + msk[m];
        sc[m] = a;
        mx = fmaxf(mx, a);
    }
    float den = 0.f;
#pragma unroll
    for (int m = 0; m < SETSZ; m++) { float e = expf(sc[m] - mx); sc[m] = e; den += e; }
    float inv = 1.0f / den;
    float o[DHEAD];
#pragma unroll
    for (int d = 0; d < DHEAD; d++) o[d] = 0.f;
#pragma unroll
    for (int m = 0; m < SETSZ; m++) {
        float a = sc[m] * inv;
#pragma unroll
        for (int d = 0; d < DHEAD; d++) o[d] += a * vs[hl][m][d];
    }
    float* op = outp + ((size_t)s * SETSZ + l) * 256 + (size_t)(h0 + hl) * DHEAD;
#pragma unroll
    for (int d4 = 0; d4 < 8; d4++)
        ((float4*)op)[d4] = make_float4(o[d4*4], o[d4*4+1], o[d4*4+2], o[d4*4+3]);
}

// ---------------------------------------------------------------------------
// LayerNorm helpers: warp-per-row, 8 elems/lane (2 x float4)
// ---------------------------------------------------------------------------
__device__ __forceinline__ float wsum(float v)
{
#pragma unroll
    for (int o = 16; o > 0; o >>= 1) v += __shfl_xor_sync(0xffffffffu, v, o);
    return v;
}

__device__ __forceinline__ void ln8(float4& v0, float4& v1,
                                    const float* __restrict__ g,
                                    const float* __restrict__ b, int lane)
{
    float s  = v0.x + v0.y + v0.z + v0.w + v1.x + v1.y + v1.z + v1.w;
    float ss = v0.x*v0.x + v0.y*v0.y + v0.z*v0.z + v0.w*v0.w
             + v1.x*v1.x + v1.y*v1.y + v1.z*v1.z + v1.w*v1.w;
    s = wsum(s); ss = wsum(ss);
    float mean = s * (1.0f / 256.0f);
    float var  = ss * (1.0f / 256.0f) - mean * mean;
    float inv  = rsqrtf(fmaxf(var, 0.0f) + 1e-5f);
    float4 G0 = ((const float4*)g)[lane];
    float4 G1 = ((const float4*)g)[lane + 32];
    float4 B0 = ((const float4*)b)[lane];
    float4 B1 = ((const float4*)b)[lane + 32];
    v0.x = (v0.x - mean) * inv * G0.x + B0.x;
    v0.y = (v0.y - mean) * inv * G0.y + B0.y;
    v0.z = (v0.z - mean) * inv * G0.z + B0.z;
    v0.w = (v0.w - mean) * inv * G0.w + B0.w;
    v1.x = (v1.x - mean) * inv * G1.x + B1.x;
    v1.y = (v1.y - mean) * inv * G1.y + B1.y;
    v1.z = (v1.z - mean) * inv * G1.z + B1.z;
    v1.w = (v1.w - mean) * inv * G1.w + B1.w;
}

__device__ __forceinline__ float4 f4add(float4 a, float4 b)
{ return make_float4(a.x + b.x, a.y + b.y, a.z + b.z, a.w + b.w); }

// out[t] = LN(x[t] + o[j]) where t = inds[j]  (bijective scatter fused)
__global__ __launch_bounds__(256) void ln1_scatter_kernel(
    const float* __restrict__ x, const float* __restrict__ o,
    const int* __restrict__ inds, const float* __restrict__ g,
    const float* __restrict__ b, float* __restrict__ out)
{
    int w = (blockIdx.x << 3) + (threadIdx.x >> 5);
    if (w >= NTOK) return;
    int lane = threadIdx.x & 31;
    int t = inds[w];
    const float4* xr  = (const float4*)(x + (size_t)t * 256);
    const float4* orr = (const float4*)(o + (size_t)w * 256);
    float4 v0 = f4add(xr[lane],      orr[lane]);
    float4 v1 = f4add(xr[lane + 32], orr[lane + 32]);
    ln8(v0, v1, g, b, lane);
    ((float4*)(out + (size_t)t * 256))[lane]      = v0;
    ((float4*)(out + (size_t)t * 256))[lane + 32] = v1;
}

// xio[t] = LN_enc( LN_2(x1[t]+ff[t]) + xio[t] )   (xio holds the identity)
__global__ __launch_bounds__(256) void ln2_enc_kernel(
    const float* __restrict__ x1, const float* __restrict__ ff,
    float* __restrict__ xio,
    const float* __restrict__ g2, const float* __restrict__ b2,
    const float* __restrict__ ge, const float* __restrict__ be)
{
    int w = (blockIdx.x << 3) + (threadIdx.x >> 5);
    if (w >= NTOK) return;
    int lane = threadIdx.x & 31;
    const float4* r1 = (const float4*)(x1 + (size_t)w * 256);
    const float4* rf = (const float4*)(ff + (size_t)w * 256);
    float4* rx = (float4*)(xio + (size_t)w * 256);
    float4 v0 = f4add(r1[lane],      rf[lane]);
    float4 v1 = f4add(r1[lane + 32], rf[lane + 32]);
    ln8(v0, v1, g2, b2, lane);
    v0 = f4add(v0, rx[lane]);
    v1 = f4add(v1, rx[lane + 32]);
    ln8(v0, v1, ge, be, lane);
    rx[lane]      = v0;
    rx[lane + 32] = v1;
}

// out[t] = LN(x[t] + r[t])
__global__ __launch_bounds__(256) void ln_res_kernel(
    const float* __restrict__ x, const float* __restrict__ r,
    const float* __restrict__ g, const float* __restrict__ b,
    float* __restrict__ out)
{
    int w = (blockIdx.x << 3) + (threadIdx.x >> 5);
    if (w >= NTOK) return;
    int lane = threadIdx.x & 31;
    const float4* xr = (const float4*)(x + (size_t)w * 256);
    const float4* rr = (const float4*)(r + (size_t)w * 256);
    float4 v0 = f4add(xr[lane],      rr[lane]);
    float4 v1 = f4add(xr[lane + 32], rr[lane + 32]);
    ln8(v0, v1, g, b, lane);
    ((float4*)(out + (size_t)w * 256))[lane]      = v0;
    ((float4*)(out + (size_t)w * 256))[lane + 32] = v1;
}

// ---------------------------------------------------------------------------
// Orchestration
// ---------------------------------------------------------------------------
extern "C" void kernel_launch(void* const* d_in, const int* in_sizes, int n_in,
                              void* d_out, int out_size)
{
    const float* src   = (const float*)d_in[0];
    const float* pos   = (const float*)d_in[1];
    const int*   inds  = (const int*)  d_in[2];
    const void*  masks =               d_in[3];
    const float* ipw   = (const float*)d_in[4];
    const float* ipb   = (const float*)d_in[5];
    const float* oww   = (const float*)d_in[6];
    const float* owb   = (const float*)d_in[7];
    const float* l1w   = (const float*)d_in[8];
    const float* l1b   = (const float*)d_in[9];
    const float* l2w   = (const float*)d_in[10];
    const float* l2b   = (const float*)d_in[11];
    const float* n1g   = (const float*)d_in[12];
    const float* n1b   = (const float*)d_in[13];
    const float* n2g   = (const float*)d_in[14];
    const float* n2b   = (const float*)d_in[15];
    const float* encg  = (const float*)d_in[16];
    const float* encb  = (const float*)d_in[17];
    const float* resg  = (const float*)d_in[18];
    const float* resb  = (const float*)d_in[19];
    float* outp = (float*)d_out;

    float *x, *res, *qk, *feat, *qkp, *v, *attn, *o, *x1, *h, *ff;
    cudaGetSymbolAddress((void**)&x,    g_x);
    cudaGetSymbolAddress((void**)&res,  g_res);
    cudaGetSymbolAddress((void**)&qk,   g_qk);
    cudaGetSymbolAddress((void**)&feat, g_feat);
    cudaGetSymbolAddress((void**)&qkp,  g_qkp);
    cudaGetSymbolAddress((void**)&v,    g_v);
    cudaGetSymbolAddress((void**)&attn, g_attn);
    cudaGetSymbolAddress((void**)&o,    g_o);
    cudaGetSymbolAddress((void**)&x1,   g_x1);
    cudaGetSymbolAddress((void**)&h,    g_h);
    cudaGetSymbolAddress((void**)&ff,   g_ff);

    const size_t xbytes = (size_t)NTOK * CDIM * sizeof(float);
    const int gM = (NTOK + 127) / 128;   // 2049

    detect_mask_kernel<<<1, 256>>>((const unsigned int*)masks,
                                   (2 * 2 * NSETS * SETSZ) / 4);
    cudaMemcpyAsync(x, src, xbytes, cudaMemcpyDeviceToDevice);

    for (int blk = 0; blk < 2; blk++) {
        cudaMemcpyAsync(res, x, xbytes, cudaMemcpyDeviceToDevice);
        for (int i = 0; i < 2; i++) {
            int lid = blk * 2 + i;   // == shift*2 + partition == pos index
            const int* ip = inds + (size_t)lid * NSETS * SETSZ;
            int moff = lid * NSETS * SETSZ;
            const float* pp = pos + (size_t)lid * NTOK * CDIM;

            gather_kernel<<<(NTOK * 64 + 255) / 256, 256>>>(x, pp, ip, qk, feat);

            // in-proj: [Q|K] from qk (512 outs), V from feat (256 outs)
            gemm_tf32x3_kernel<<<dim3(gM, 4), 256>>>(
                qk, ipw + (size_t)lid * 768 * 256, ipb + (size_t)lid * 768,
                qkp, NTOK, 512, 256, 0);
            gemm_tf32x3_kernel<<<dim3(gM, 2), 256>>>(
                feat, ipw + (size_t)lid * 768 * 256 + 512 * 256,
                ipb + (size_t)lid * 768 + 512, v, NTOK, 256, 256, 0);

            attn_kernel<<<dim3(NSETS, 2), 144>>>(qkp, v, masks, moff, attn);

            gemm_tf32x3_kernel<<<dim3(gM, 2), 256>>>(
                attn, oww + (size_t)lid * 256 * 256, owb + (size_t)lid * 256,
                o, NTOK, 256, 256, 0);

            ln1_scatter_kernel<<<(NTOK + 7) / 8, 256>>>(
                x, o, ip, n1g + (size_t)lid * 256, n1b + (size_t)lid * 256, x1);

            gemm_tf32x3_kernel<<<dim3(gM, 8), 256>>>(
                x1, l1w + (size_t)lid * 1024 * 256, l1b + (size_t)lid * 1024,
                h, NTOK, 1024, 256, 1);
            gemm_tf32x3_kernel<<<dim3(gM, 2), 256>>>(
                h, l2w + (size_t)lid * 256 * 1024, l2b + (size_t)lid * 256,
                ff, NTOK, 256, 1024, 0);

            ln2_enc_kernel<<<(NTOK + 7) / 8, 256>>>(
                x1, ff, x,
                n2g + (size_t)lid * 256, n2b + (size_t)lid * 256,
                encg + (size_t)lid * 256, encb + (size_t)lid * 256);
        }
        float* dst = (blk == 1) ? outp : x;
        ln_res_kernel<<<(NTOK + 7) / 8, 256>>>(
            x, res, resg + (size_t)blk * 256, resb + (size_t)blk * 256, dst);
    }
}

// round 4
// speedup vs baseline: 2.2445x; 2.2445x over previous
#include <cuda_runtime.h>
#include <cuda_bf16.h>
#include <mma.h>
#include <cstdint>
#include <cmath>

using namespace nvcuda;

#define NTOK   262152
#define CDIM   256
#define NSETS  7282
#define SETSZ  36
#define NHEAD  8
#define DHEAD  32
#define DFFN   1024

// ---------------------------------------------------------------------------
// Single workspace (total < 4GB for aarch64 .bss relocation range).
// Aliasing (safe under stream order):
//   v == o == ff           (fp32, each dead before next write)
//   x1  lives in qkp space (qkp dead after attention)
//   x1b == qkb, attnb == featb
//   hb chunked over M (halves)
// ---------------------------------------------------------------------------
#define SZ_C   ((size_t)NTOK * 256 * 4)          // 268,443,648
#define SZ_B   ((size_t)NTOK * 768 * 2)          // 402,665,472
#define CH0    131072
#define CH1    (NTOK - CH0)                      // 131,080
#define SZ_HB  ((size_t)CH1 * 3072 * 2)          // 805,355,520

#define OFF_X    ((size_t)0)
#define OFF_RES  (OFF_X   + SZ_C)
#define OFF_QKP  (OFF_RES + SZ_C)                // 2*SZ_C; x1 aliases here
#define OFF_VOF  (OFF_QKP + 2 * SZ_C)            // v / o / ff
#define OFF_BUFA (OFF_VOF + SZ_C)                // qkb / x1b
#define OFF_BUFB (OFF_BUFA + SZ_B)               // featb / attnb
#define OFF_HB   (OFF_BUFB + SZ_B)
#define OFF_WIP  (OFF_HB  + SZ_HB)               // ipwb 4*768*768*2
#define OFF_WOW  (OFF_WIP + (size_t)4*768*768*2)
#define OFF_WL1  (OFF_WOW + (size_t)4*256*768*2)
#define OFF_WL2  (OFF_WL1 + (size_t)4*1024*768*2)
#define WS_TOT   (OFF_WL2 + (size_t)4*256*3072*2)   // ~2.97 GB

__device__ __align__(256) char g_ws[WS_TOT];
__device__ int g_mask_mode;

// ---------------------------------------------------------------------------
// Helpers
// ---------------------------------------------------------------------------
__device__ __forceinline__ uint32_t smem_u32(const void* p) {
    uint32_t a;
    asm("{ .reg .u64 t; cvta.to.shared.u64 t, %1; cvt.u32.u64 %0, t; }"
        : "=r"(a) : "l"(p));
    return a;
}
__device__ __forceinline__ void cp16(uint32_t dst, const void* src, int sz) {
    asm volatile("cp.async.cg.shared.global [%0], [%1], 16, %2;"
                 :: "r"(dst), "l"(src), "r"(sz) : "memory");
}
#define CP_COMMIT() asm volatile("cp.async.commit_group;" ::: "memory")
#define CP_WAIT2()  asm volatile("cp.async.wait_group 2;" ::: "memory")

__device__ __forceinline__ uint32_t pack2bf(__nv_bfloat16 a, __nv_bfloat16 b) {
    __nv_bfloat162 h;
    h.x = a; h.y = b;
    return *reinterpret_cast<uint32_t*>(&h);
}
__device__ __forceinline__ void split4(float4 v, uint32_t& h01, uint32_t& h23,
                                       uint32_t& l01, uint32_t& l23) {
    __nv_bfloat16 hx = __float2bfloat16(v.x), hy = __float2bfloat16(v.y);
    __nv_bfloat16 hz = __float2bfloat16(v.z), hw = __float2bfloat16(v.w);
    float lx = v.x - __bfloat162float(hx), ly = v.y - __bfloat162float(hy);
    float lz = v.z - __bfloat162float(hz), lw = v.w - __bfloat162float(hw);
    h01 = pack2bf(hx, hy); h23 = pack2bf(hz, hw);
    l01 = pack2bf(__float2bfloat16(lx), __float2bfloat16(ly));
    l23 = pack2bf(__float2bfloat16(lz), __float2bfloat16(lw));
}
// activation aug row [hi | lo | hi], row stride 3K
__device__ __forceinline__ void write4_aug(__nv_bfloat16* row, int K, int col,
                                           float4 v) {
    uint32_t h01, h23, l01, l23;
    split4(v, h01, h23, l01, l23);
    *(uint2*)(row + col)         = make_uint2(h01, h23);
    *(uint2*)(row + K + col)     = make_uint2(l01, l23);
    *(uint2*)(row + 2 * K + col) = make_uint2(h01, h23);
}

// ---------------------------------------------------------------------------
// Weight converter: W[rows x K] fp32 -> Waug[rows x 3K] bf16 [hi | hi | lo]
// ---------------------------------------------------------------------------
__global__ __launch_bounds__(256) void wconv_kernel(
    const float* __restrict__ src, __nv_bfloat16* __restrict__ dst,
    int rows, int K)
{
    int idx = blockIdx.x * 256 + threadIdx.x;
    if (idx >= rows * K) return;
    int r = idx / K, c = idx - r * K;
    float v = src[idx];
    __nv_bfloat16 hi = __float2bfloat16(v);
    float lo = v - __bfloat162float(hi);
    size_t b = (size_t)r * 3 * K;
    dst[b + c]         = hi;
    dst[b + K + c]     = hi;
    dst[b + 2 * K + c] = __float2bfloat16(lo);
}

// ---------------------------------------------------------------------------
// Mask dtype detector
// ---------------------------------------------------------------------------
__global__ void detect_mask_kernel(const unsigned int* __restrict__ w, int nwords)
{
    __shared__ int f32f, u8f;
    if (threadIdx.x == 0) { f32f = 0; u8f = 0; }
    __syncthreads();
    int lf = 0, lu = 0;
    for (int i = threadIdx.x; i < nwords; i += blockDim.x) {
        unsigned int x = w[i];
        if (x == 0x3F800000u) lf = 1;
        else if (x > 1u)      lu = 1;
    }
    if (lf) f32f = 1;
    if (lu) u8f = 1;
    __syncthreads();
    if (threadIdx.x == 0) g_mask_mode = f32f ? 2 : (u8f ? 1 : 0);
}

// ---------------------------------------------------------------------------
// Gather: aug-bf16 qk (= x[inds]+pos[inds]) and feat (= x[inds])
// ---------------------------------------------------------------------------
__global__ __launch_bounds__(256) void gather_aug_kernel(
    const float* __restrict__ x, const float* __restrict__ pos,
    const int* __restrict__ inds, __nv_bfloat16* __restrict__ qkb,
    __nv_bfloat16* __restrict__ featb)
{
    int idx = blockIdx.x * 256 + threadIdx.x;
    if (idx >= NTOK * 64) return;
    int j  = idx >> 6;
    int c4 = idx & 63;
    int t  = inds[j];
    float4 xv = ((const float4*)x)  [(size_t)t * 64 + c4];
    float4 pv = ((const float4*)pos)[(size_t)t * 64 + c4];
    float4 q  = make_float4(xv.x + pv.x, xv.y + pv.y, xv.z + pv.z, xv.w + pv.w);
    write4_aug(featb + (size_t)j * 768, 256, c4 * 4, xv);
    write4_aug(qkb   + (size_t)j * 768, 256, c4 * 4, q);
}

// ---------------------------------------------------------------------------
// bf16x3-compensated GEMM (plain bf16 wmma over augmented K' = 3K)
// CTA 128x128, BK=32, 4-stage cp.async pipeline, 8 warps of m32 x n64.
// ---------------------------------------------------------------------------
#define STAGES  4
#define STAGE_B 20480
#define SCR_OFF (STAGES * STAGE_B)
#define GSMEM   (SCR_OFF + 8 * 16 * 24 * 4)

__global__ __launch_bounds__(256, 2) void gemm_bf16_kernel(
    const __nv_bfloat16* __restrict__ A, const __nv_bfloat16* __restrict__ W,
    const float* __restrict__ bias, float* __restrict__ Cf,
    __nv_bfloat16* __restrict__ Caug, int M, int N, int K3, int act)
{
    extern __shared__ char smem[];
    const uint32_t sb = smem_u32(smem);
    const int tid  = threadIdx.x;
    const int wid  = tid >> 5;
    const int lane = tid & 31;
    const int wr   = wid >> 1;
    const int wc   = wid & 1;
    const int m0   = blockIdx.y * 128;
    const int n0   = blockIdx.x * 128;
    const int NC   = K3 >> 5;

    wmma::fragment<wmma::accumulator, 16, 16, 16, float> acc[2][4];
#pragma unroll
    for (int i = 0; i < 2; i++)
#pragma unroll
        for (int j = 0; j < 4; j++) wmma::fill_fragment(acc[i][j], 0.0f);

    auto load_stage = [&](int slot, int c) {
        const int k0 = c << 5;
#pragma unroll
        for (int it = 0; it < 2; it++) {
            int i  = tid + it * 256;
            int r  = i >> 2;
            int ch = i & 3;
            int gr = m0 + r;
            const __nv_bfloat16* sa =
                A + (size_t)(gr < M ? gr : M - 1) * K3 + k0 + ch * 8;
            cp16(sb + slot * STAGE_B + r * 80 + ch * 16, sa, gr < M ? 16 : 0);
            const __nv_bfloat16* sw = W + (size_t)(n0 + r) * K3 + k0 + ch * 8;
            cp16(sb + slot * STAGE_B + 10240 + r * 80 + ch * 16, sw, 16);
        }
    };

#pragma unroll
    for (int s = 0; s < STAGES - 1; s++) { load_stage(s, s); CP_COMMIT(); }

    for (int c = 0; c < NC; c++) {
        CP_WAIT2();
        __syncthreads();
        const int slot = c & 3;
        const __nv_bfloat16* sA =
            (const __nv_bfloat16*)(smem + slot * STAGE_B);
        const __nv_bfloat16* sB =
            (const __nv_bfloat16*)(smem + slot * STAGE_B + 10240);
#pragma unroll
        for (int kk = 0; kk < 2; kk++) {
            wmma::fragment<wmma::matrix_a, 16, 16, 16, __nv_bfloat16,
                           wmma::row_major> a[2];
            wmma::fragment<wmma::matrix_b, 16, 16, 16, __nv_bfloat16,
                           wmma::col_major> b[4];
#pragma unroll
            for (int i = 0; i < 2; i++)
                wmma::load_matrix_sync(a[i], sA + (wr * 32 + i * 16) * 40 + kk * 16, 40);
#pragma unroll
            for (int j = 0; j < 4; j++)
                wmma::load_matrix_sync(b[j], sB + (wc * 64 + j * 16) * 40 + kk * 16, 40);
#pragma unroll
            for (int i = 0; i < 2; i++)
#pragma unroll
                for (int j = 0; j < 4; j++)
                    wmma::mma_sync(acc[i][j], a[i], b[j], acc[i][j]);
        }
        __syncthreads();
        const int cn = c + STAGES - 1;
        if (cn < NC) load_stage(cn & 3, cn);
        CP_COMMIT();
    }

    float* scr = (float*)(smem + SCR_OFF) + wid * 16 * 24;
#pragma unroll
    for (int i = 0; i < 2; i++)
#pragma unroll
        for (int j = 0; j < 4; j++) {
            wmma::store_matrix_sync(scr, acc[i][j], 24, wmma::mem_row_major);
            __syncwarp();
            int r  = lane >> 1;
            int ch = (lane & 1) * 8;
            int gr = m0 + wr * 32 + i * 16 + r;
            int gc = n0 + wc * 64 + j * 16 + ch;
            if (gr < M) {
                float4 b0 = *(const float4*)(bias + gc);
                float4 b1 = *(const float4*)(bias + gc + 4);
                float v[8];
                v[0] = scr[r * 24 + ch + 0] + b0.x;
                v[1] = scr[r * 24 + ch + 1] + b0.y;
                v[2] = scr[r * 24 + ch + 2] + b0.z;
                v[3] = scr[r * 24 + ch + 3] + b0.w;
                v[4] = scr[r * 24 + ch + 4] + b1.x;
                v[5] = scr[r * 24 + ch + 5] + b1.y;
                v[6] = scr[r * 24 + ch + 6] + b1.z;
                v[7] = scr[r * 24 + ch + 7] + b1.w;
                if (act) {
#pragma unroll
                    for (int e = 0; e < 8; e++)
                        v[e] = 0.5f * v[e] *
                               (1.0f + erff(v[e] * 0.70710678118654752f));
                }
                if (Cf) {
                    float* cp = Cf + (size_t)gr * N + gc;
                    *(float4*)cp       = make_float4(v[0], v[1], v[2], v[3]);
                    *(float4*)(cp + 4) = make_float4(v[4], v[5], v[6], v[7]);
                }
                if (Caug) {
                    __nv_bfloat16* ar = Caug + (size_t)gr * 3 * N;
                    write4_aug(ar, N, gc,     make_float4(v[0], v[1], v[2], v[3]));
                    write4_aug(ar, N, gc + 4, make_float4(v[4], v[5], v[6], v[7]));
                }
            }
            __syncwarp();
        }
}

// ---------------------------------------------------------------------------
// Set attention (fp32 exact); writes aug-bf16 output
// ---------------------------------------------------------------------------
__global__ __launch_bounds__(144, 1) void attn_kernel(
    const float* __restrict__ qkp, const float* __restrict__ vb,
    const void* __restrict__ maskp, int mask_off,
    __nv_bfloat16* __restrict__ outb)
{
    const int s   = blockIdx.x;
    const int h0  = blockIdx.y * 4;
    const int tid = threadIdx.x;
    const int hl  = tid / SETSZ;
    const int l   = tid - hl * SETSZ;

    __shared__ float ks[4][SETSZ][DHEAD];
    __shared__ float vs[4][SETSZ][DHEAD];
    __shared__ float msk[SETSZ];

    if (tid < SETSZ) {
        int gi = mask_off + s * SETSZ + tid;
        int mode = g_mask_mode;
        bool m;
        if (mode == 0)      m = ((const int*)maskp)[gi] != 0;
        else if (mode == 1) m = ((const unsigned char*)maskp)[gi] != 0;
        else                m = ((const float*)maskp)[gi] != 0.0f;
        msk[tid] = m ? -INFINITY : 0.0f;
    }
    for (int idx = tid; idx < 4 * SETSZ * DHEAD; idx += 144) {
        int d  = idx & (DHEAD - 1);
        int m  = (idx >> 5) % SETSZ;
        int hh = idx / (DHEAD * SETSZ);
        size_t row = (size_t)s * SETSZ + m;
        ks[hh][m][d] = qkp[row * 512 + 256 + (size_t)(h0 + hh) * DHEAD + d];
        vs[hh][m][d] = vb [row * 256 +       (size_t)(h0 + hh) * DHEAD + d];
    }
    __syncthreads();

    float q[DHEAD];
    {
        const float4* qr = (const float4*)(qkp + ((size_t)s * SETSZ + l) * 512
                                           + (size_t)(h0 + hl) * DHEAD);
#pragma unroll
        for (int d4 = 0; d4 < 8; d4++) {
            float4 vq = qr[d4];
            q[d4*4+0] = vq.x; q[d4*4+1] = vq.y; q[d4*4+2] = vq.z; q[d4*4+3] = vq.w;
        }
    }
    const float scale = 0.17677669529663687f;
    float sc[SETSZ];
    float mx = -INFINITY;
#pragma unroll
    for (int m = 0; m < SETSZ; m++) {
        float a = 0.f;
#pragma unroll
        for (int d = 0; d < DHEAD; d++) a += q[d] * ks[hl][m][d];
        a = a * scale + msk[m];
        sc[m] = a;
        mx = fmaxf(mx, a);
    }
    float den = 0.f;
#pragma unroll
    for (int m = 0; m < SETSZ; m++) { float e = expf(sc[m] - mx); sc[m] = e; den += e; }
    float inv = 1.0f / den;
    float o[DHEAD];
#pragma unroll
    for (int d = 0; d < DHEAD; d++) o[d] = 0.f;
#pragma unroll
    for (int m = 0; m < SETSZ; m++) {
        float a = sc[m] * inv;
#pragma unroll
        for (int d = 0; d < DHEAD; d++) o[d] += a * vs[hl][m][d];
    }
    __nv_bfloat16* op = outb + ((size_t)s * SETSZ + l) * 768;
    int col = (h0 + hl) * DHEAD;
#pragma unroll
    for (int p = 0; p < 8; p++)
        write4_aug(op, 256, col + p * 4,
                   make_float4(o[p*4], o[p*4+1], o[p*4+2], o[p*4+3]));
}

// ---------------------------------------------------------------------------
// LayerNorm helpers
// ---------------------------------------------------------------------------
__device__ __forceinline__ float wsum(float v)
{
#pragma unroll
    for (int o = 16; o > 0; o >>= 1) v += __shfl_xor_sync(0xffffffffu, v, o);
    return v;
}

__device__ __forceinline__ void ln8(float4& v0, float4& v1,
                                    const float* __restrict__ g,
                                    const float* __restrict__ b, int lane)
{
    float s  = v0.x + v0.y + v0.z + v0.w + v1.x + v1.y + v1.z + v1.w;
    float ss = v0.x*v0.x + v0.y*v0.y + v0.z*v0.z + v0.w*v0.w
             + v1.x*v1.x + v1.y*v1.y + v1.z*v1.z + v1.w*v1.w;
    s = wsum(s); ss = wsum(ss);
    float mean = s * (1.0f / 256.0f);
    float var  = ss * (1.0f / 256.0f) - mean * mean;
    float inv  = rsqrtf(fmaxf(var, 0.0f) + 1e-5f);
    float4 G0 = ((const float4*)g)[lane];
    float4 G1 = ((const float4*)g)[lane + 32];
    float4 B0 = ((const float4*)b)[lane];
    float4 B1 = ((const float4*)b)[lane + 32];
    v0.x = (v0.x - mean) * inv * G0.x + B0.x;
    v0.y = (v0.y - mean) * inv * G0.y + B0.y;
    v0.z = (v0.z - mean) * inv * G0.z + B0.z;
    v0.w = (v0.w - mean) * inv * G0.w + B0.w;
    v1.x = (v1.x - mean) * inv * G1.x + B1.x;
    v1.y = (v1.y - mean) * inv * G1.y + B1.y;
    v1.z = (v1.z - mean) * inv * G1.z + B1.z;
    v1.w = (v1.w - mean) * inv * G1.w + B1.w;
}

__device__ __forceinline__ float4 f4add(float4 a, float4 b)
{ return make_float4(a.x + b.x, a.y + b.y, a.z + b.z, a.w + b.w); }

__global__ __launch_bounds__(256) void ln1_scatter_kernel(
    const float* __restrict__ x, const float* __restrict__ o,
    const int* __restrict__ inds, const float* __restrict__ g,
    const float* __restrict__ b, float* __restrict__ out,
    __nv_bfloat16* __restrict__ outb)
{
    int w = (blockIdx.x << 3) + (threadIdx.x >> 5);
    if (w >= NTOK) return;
    int lane = threadIdx.x & 31;
    int t = inds[w];
    const float4* xr  = (const float4*)(x + (size_t)t * 256);
    const float4* orr = (const float4*)(o + (size_t)w * 256);
    float4 v0 = f4add(xr[lane],      orr[lane]);
    float4 v1 = f4add(xr[lane + 32], orr[lane + 32]);
    ln8(v0, v1, g, b, lane);
    ((float4*)(out + (size_t)t * 256))[lane]      = v0;
    ((float4*)(out + (size_t)t * 256))[lane + 32] = v1;
    __nv_bfloat16* ar = outb + (size_t)t * 768;
    write4_aug(ar, 256, lane * 4,       v0);
    write4_aug(ar, 256, 128 + lane * 4, v1);
}

__global__ __launch_bounds__(256) void ln2_enc_kernel(
    const float* __restrict__ x1, const float* __restrict__ ff,
    float* __restrict__ xio,
    const float* __restrict__ g2, const float* __restrict__ b2,
    const float* __restrict__ ge, const float* __restrict__ be)
{
    int w = (blockIdx.x << 3) + (threadIdx.x >> 5);
    if (w >= NTOK) return;
    int lane = threadIdx.x & 31;
    const float4* r1 = (const float4*)(x1 + (size_t)w * 256);
    const float4* rf = (const float4*)(ff + (size_t)w * 256);
    float4* rx = (float4*)(xio + (size_t)w * 256);
    float4 v0 = f4add(r1[lane],      rf[lane]);
    float4 v1 = f4add(r1[lane + 32], rf[lane + 32]);
    ln8(v0, v1, g2, b2, lane);
    v0 = f4add(v0, rx[lane]);
    v1 = f4add(v1, rx[lane + 32]);
    ln8(v0, v1, ge, be, lane);
    rx[lane]      = v0;
    rx[lane + 32] = v1;
}

__global__ __launch_bounds__(256) void ln_res_kernel(
    const float* __restrict__ x, const float* __restrict__ r,
    const float* __restrict__ g, const float* __restrict__ b,
    float* __restrict__ out)
{
    int w = (blockIdx.x << 3) + (threadIdx.x >> 5);
    if (w >= NTOK) return;
    int lane = threadIdx.x & 31;
    const float4* xr = (const float4*)(x + (size_t)w * 256);
    const float4* rr = (const float4*)(r + (size_t)w * 256);
    float4 v0 = f4add(xr[lane],      rr[lane]);
    float4 v1 = f4add(xr[lane + 32], rr[lane + 32]);
    ln8(v0, v1, g, b, lane);
    ((float4*)(out + (size_t)w * 256))[lane]      = v0;
    ((float4*)(out + (size_t)w * 256))[lane + 32] = v1;
}

// ---------------------------------------------------------------------------
// Orchestration
// ---------------------------------------------------------------------------
extern "C" void kernel_launch(void* const* d_in, const int* in_sizes, int n_in,
                              void* d_out, int out_size)
{
    const float* src   = (const float*)d_in[0];
    const float* pos   = (const float*)d_in[1];
    const int*   inds  = (const int*)  d_in[2];
    const void*  masks =               d_in[3];
    const float* ipw   = (const float*)d_in[4];
    const float* ipb   = (const float*)d_in[5];
    const float* oww   = (const float*)d_in[6];
    const float* owb   = (const float*)d_in[7];
    const float* l1w   = (const float*)d_in[8];
    const float* l1b   = (const float*)d_in[9];
    const float* l2w   = (const float*)d_in[10];
    const float* l2b   = (const float*)d_in[11];
    const float* n1g   = (const float*)d_in[12];
    const float* n1b   = (const float*)d_in[13];
    const float* n2g   = (const float*)d_in[14];
    const float* n2b   = (const float*)d_in[15];
    const float* encg  = (const float*)d_in[16];
    const float* encb  = (const float*)d_in[17];
    const float* resg  = (const float*)d_in[18];
    const float* resb  = (const float*)d_in[19];
    float* outp = (float*)d_out;

    char* ws;
    cudaGetSymbolAddress((void**)&ws, g_ws);
    float* x    = (float*)(ws + OFF_X);
    float* res  = (float*)(ws + OFF_RES);
    float* qkp  = (float*)(ws + OFF_QKP);
    float* x1   = (float*)(ws + OFF_QKP);         // alias (qkp dead by then)
    float* v    = (float*)(ws + OFF_VOF);
    float* o    = (float*)(ws + OFF_VOF);
    float* ff   = (float*)(ws + OFF_VOF);
    __nv_bfloat16* qkb   = (__nv_bfloat16*)(ws + OFF_BUFA);
    __nv_bfloat16* x1b   = (__nv_bfloat16*)(ws + OFF_BUFA);
    __nv_bfloat16* featb = (__nv_bfloat16*)(ws + OFF_BUFB);
    __nv_bfloat16* attnb = (__nv_bfloat16*)(ws + OFF_BUFB);
    __nv_bfloat16* hb    = (__nv_bfloat16*)(ws + OFF_HB);
    __nv_bfloat16* ipwb  = (__nv_bfloat16*)(ws + OFF_WIP);
    __nv_bfloat16* owwb  = (__nv_bfloat16*)(ws + OFF_WOW);
    __nv_bfloat16* l1wb  = (__nv_bfloat16*)(ws + OFF_WL1);
    __nv_bfloat16* l2wb  = (__nv_bfloat16*)(ws + OFF_WL2);

    cudaFuncSetAttribute(gemm_bf16_kernel,
                         cudaFuncAttributeMaxDynamicSharedMemorySize, GSMEM);

    const size_t xbytes = (size_t)NTOK * CDIM * sizeof(float);
    const int gM = (NTOK + 127) / 128;

    detect_mask_kernel<<<1, 256>>>((const unsigned int*)masks,
                                   (2 * 2 * NSETS * SETSZ) / 4);
    wconv_kernel<<<(4 * 768 * 256 + 255) / 256, 256>>>(ipw, ipwb, 4 * 768, 256);
    wconv_kernel<<<(4 * 256 * 256 + 255) / 256, 256>>>(oww, owwb, 4 * 256, 256);
    wconv_kernel<<<(4 * 1024 * 256 + 255) / 256, 256>>>(l1w, l1wb, 4 * 1024, 256);
    wconv_kernel<<<(4 * 256 * 1024 + 255) / 256, 256>>>(l2w, l2wb, 4 * 256, 1024);

    cudaMemcpyAsync(x, src, xbytes, cudaMemcpyDeviceToDevice);

    for (int blk = 0; blk < 2; blk++) {
        cudaMemcpyAsync(res, x, xbytes, cudaMemcpyDeviceToDevice);
        for (int i = 0; i < 2; i++) {
            int lid = blk * 2 + i;
            const int* ip = inds + (size_t)lid * NSETS * SETSZ;
            int moff = lid * NSETS * SETSZ;
            const float* pp = pos + (size_t)lid * NTOK * CDIM;

            gather_aug_kernel<<<(NTOK * 64 + 255) / 256, 256>>>(
                x, pp, ip, qkb, featb);

            gemm_bf16_kernel<<<dim3(4, gM), 256, GSMEM>>>(
                qkb, ipwb + (size_t)lid * 768 * 768, ipb + (size_t)lid * 768,
                qkp, nullptr, NTOK, 512, 768, 0);
            gemm_bf16_kernel<<<dim3(2, gM), 256, GSMEM>>>(
                featb, ipwb + (size_t)lid * 768 * 768 + (size_t)512 * 768,
                ipb + (size_t)lid * 768 + 512, v, nullptr, NTOK, 256, 768, 0);

            attn_kernel<<<dim3(NSETS, 2), 144>>>(qkp, v, masks, moff, attnb);

            gemm_bf16_kernel<<<dim3(2, gM), 256, GSMEM>>>(
                attnb, owwb + (size_t)lid * 256 * 768, owb + (size_t)lid * 256,
                o, nullptr, NTOK, 256, 768, 0);

            ln1_scatter_kernel<<<(NTOK + 7) / 8, 256>>>(
                x, o, ip, n1g + (size_t)lid * 256, n1b + (size_t)lid * 256,
                x1, x1b);

            // FFN in two M-chunks to halve the hidden buffer
            for (int ch = 0; ch < 2; ch++) {
                int mo  = ch ? CH0 : 0;
                int mm  = ch ? CH1 : CH0;
                int gMc = (mm + 127) / 128;
                gemm_bf16_kernel<<<dim3(8, gMc), 256, GSMEM>>>(
                    x1b + (size_t)mo * 768,
                    l1wb + (size_t)lid * 1024 * 768, l1b + (size_t)lid * 1024,
                    nullptr, hb, mm, 1024, 768, 1);
                gemm_bf16_kernel<<<dim3(2, gMc), 256, GSMEM>>>(
                    hb, l2wb + (size_t)lid * 256 * 3072, l2b + (size_t)lid * 256,
                    ff + (size_t)mo * 256, nullptr, mm, 256, 3072, 0);
            }

            ln2_enc_kernel<<<(NTOK + 7) / 8, 256>>>(
                x1, ff, x,
                n2g + (size_t)lid * 256, n2b + (size_t)lid * 256,
                encg + (size_t)lid * 256, encb + (size_t)lid * 256);
        }
        float* dst = (blk == 1) ? outp : x;
        ln_res_kernel<<<(NTOK + 7) / 8, 256>>>(
            x, res, resg + (size_t)blk * 256, resb + (size_t)blk * 256, dst);
    }
}

// round 6
// speedup vs baseline: 3.7330x; 1.6632x over previous
#include <cuda_runtime.h>
#include <cuda_fp16.h>
#include <mma.h>
#include <cstdint>
#include <cmath>

using namespace nvcuda;

#define NTOK   262152
#define CDIM   256
#define NSETS  7282
#define SETSZ  36
#define NHEAD  8
#define DHEAD  32
#define DFFN   1024

// ---------------------------------------------------------------------------
// Workspace (single symbol, < 4GB for aarch64 .bss reloc range). ~2.16 GB.
// Aliases (stream-order safe): v==o==ff; x1 in qkp space; x1b==qkb; attnb==featb
// ---------------------------------------------------------------------------
#define SZ_C   ((size_t)NTOK * 256 * 4)
#define SZ_H   ((size_t)NTOK * 256 * 2)
#define OFF_X    ((size_t)0)
#define OFF_RES  (OFF_X   + SZ_C)
#define OFF_QKP  (OFF_RES + SZ_C)          // fp32 NTOK x 512 (x1 aliases)
#define OFF_VOF  (OFF_QKP + 2 * SZ_C)      // v / o / ff
#define OFF_QKB  (OFF_VOF + SZ_C)          // fp16 NTOK x 256 (x1b aliases)
#define OFF_FEB  (OFF_QKB + SZ_H)          // fp16 NTOK x 256 (attnb aliases)
#define OFF_HB   (OFF_FEB + SZ_H)          // fp16 NTOK x 1024
#define OFF_WIP  (OFF_HB  + (size_t)NTOK * 1024 * 2)
#define OFF_WOW  (OFF_WIP + (size_t)4*768*512*2)
#define OFF_WL1  (OFF_WOW + (size_t)4*256*512*2)
#define OFF_WL2  (OFF_WL1 + (size_t)4*1024*512*2)
#define WS_TOT   (OFF_WL2 + (size_t)4*256*2048*2)

__device__ __align__(256) char g_ws[WS_TOT];
__device__ int g_mask_mode;

// ---------------------------------------------------------------------------
// Helpers
// ---------------------------------------------------------------------------
__device__ __forceinline__ uint32_t smem_u32(const void* p) {
    uint32_t a;
    asm("{ .reg .u64 t; cvta.to.shared.u64 t, %1; cvt.u32.u64 %0, t; }"
        : "=r"(a) : "l"(p));
    return a;
}
__device__ __forceinline__ void cp16(uint32_t dst, const void* src, int sz) {
    asm volatile("cp.async.cg.shared.global [%0], [%1], 16, %2;"
                 :: "r"(dst), "l"(src), "r"(sz) : "memory");
}
#define CP_COMMIT() asm volatile("cp.async.commit_group;" ::: "memory")
#define CP_WAIT1()  asm volatile("cp.async.wait_group 1;" ::: "memory")
#define CP_WAIT0()  asm volatile("cp.async.wait_group 0;" ::: "memory")

__device__ __forceinline__ uint32_t pack2h(float a, float b) {
    __half2 h;
    h.x = __float2half_rn(a); h.y = __float2half_rn(b);
    return *reinterpret_cast<uint32_t*>(&h);
}
__device__ __forceinline__ void write4h(__half* p, float4 v) {
    *(uint2*)p = make_uint2(pack2h(v.x, v.y), pack2h(v.z, v.w));
}

// ---------------------------------------------------------------------------
// Weight converter: W[rows x K] fp32 -> [Wh | Wl] fp16, row stride 2K
// ---------------------------------------------------------------------------
__global__ __launch_bounds__(256) void wconv_kernel(
    const float* __restrict__ src, __half* __restrict__ dst, int rows, int K)
{
    int idx = blockIdx.x * 256 + threadIdx.x;
    if (idx >= rows * K) return;
    int r = idx / K, c = idx - r * K;
    float v = src[idx];
    __half hi = __float2half_rn(v);
    float lo = v - __half2float(hi);
    size_t b = (size_t)r * 2 * K;
    dst[b + c]     = hi;
    dst[b + K + c] = __float2half_rn(lo);
}

// ---------------------------------------------------------------------------
// Mask dtype detector
// ---------------------------------------------------------------------------
__global__ void detect_mask_kernel(const unsigned int* __restrict__ w, int nwords)
{
    __shared__ int f32f, u8f;
    if (threadIdx.x == 0) { f32f = 0; u8f = 0; }
    __syncthreads();
    int lf = 0, lu = 0;
    for (int i = threadIdx.x; i < nwords; i += blockDim.x) {
        unsigned int x = w[i];
        if (x == 0x3F800000u) lf = 1;
        else if (x > 1u)      lu = 1;
    }
    if (lf) f32f = 1;
    if (lu) u8f = 1;
    __syncthreads();
    if (threadIdx.x == 0) g_mask_mode = f32f ? 2 : (u8f ? 1 : 0);
}

// ---------------------------------------------------------------------------
// Gather: fp16 qk (= x[inds]+pos[inds]) and feat (= x[inds])
// ---------------------------------------------------------------------------
__global__ __launch_bounds__(256) void gather_kernel(
    const float* __restrict__ x, const float* __restrict__ pos,
    const int* __restrict__ inds, __half* __restrict__ qkb,
    __half* __restrict__ featb)
{
    int idx = blockIdx.x * 256 + threadIdx.x;
    if (idx >= NTOK * 64) return;
    int j  = idx >> 6;
    int c4 = idx & 63;
    int t  = inds[j];
    float4 xv = ((const float4*)x)  [(size_t)t * 64 + c4];
    float4 pv = ((const float4*)pos)[(size_t)t * 64 + c4];
    float4 q  = make_float4(xv.x + pv.x, xv.y + pv.y, xv.z + pv.z, xv.w + pv.w);
    write4h(featb + (size_t)j * 256 + c4 * 4, xv);
    write4h(qkb   + (size_t)j * 256 + c4 * 4, q);
}

// ---------------------------------------------------------------------------
// fp16 exact-weight GEMM: C[m,n] = fp16(A[m,:]) . W[n,:] + bias[n] (+GELU)
// W stored [Wh | Wl] stride 2*KA; A plain fp16 stride KA, virtually repeated
// over the two K-halves. K_mma = 2*KA. CTA 128x128, BK=64, 3-stage cp.async.
// ---------------------------------------------------------------------------
#define STAGE_B 36864          // A 128x144B + B 128x144B
#define GSMEM   (3 * STAGE_B)  // 110592; epilogue scratch aliases stage 0

__global__ __launch_bounds__(256, 2) void gemm_fp16_kernel(
    const __half* __restrict__ A, int KA,
    const __half* __restrict__ W, const float* __restrict__ bias,
    float* __restrict__ Cf, __half* __restrict__ Ch,
    int M, int N, int act)
{
    extern __shared__ char smem[];
    const uint32_t sb = smem_u32(smem);
    const int tid  = threadIdx.x;
    const int wid  = tid >> 5;
    const int lane = tid & 31;
    const int wr   = wid >> 1;   // 0..3
    const int wc   = wid & 1;    // 0..1
    const int m0   = blockIdx.y * 128;
    const int n0   = blockIdx.x * 128;
    const int KW   = 2 * KA;
    const int NC   = KW >> 6;    // BK=64 chunks over K_mma

    wmma::fragment<wmma::accumulator, 16, 16, 16, float> acc[2][4];
#pragma unroll
    for (int i = 0; i < 2; i++)
#pragma unroll
        for (int j = 0; j < 4; j++) wmma::fill_fragment(acc[i][j], 0.0f);

    // Fill one stage: 128 rows x 128B for A and W (8 x 16B chunks per row).
    auto load_stage = [&](int slot, int c) {
        const int k0 = c << 6;
        const int ka = (k0 >= KA) ? k0 - KA : k0;   // A virtual repeat
        const uint32_t base = sb + slot * STAGE_B;
#pragma unroll
        for (int it = 0; it < 4; it++) {
            int i  = tid + it * 256;      // 0..1023
            int r  = i >> 3;              // row 0..127
            int ch = i & 7;               // 16B chunk 0..7
            int gr = m0 + r;
            const __half* sa =
                A + (size_t)(gr < M ? gr : M - 1) * KA + ka + ch * 8;
            cp16(base + r * 144 + ch * 16, sa, gr < M ? 16 : 0);
            const __half* sw = W + (size_t)(n0 + r) * KW + k0 + ch * 8;
            cp16(base + 18432 + r * 144 + ch * 16, sw, 16);
        }
    };

    load_stage(0, 0); CP_COMMIT();
    load_stage(1, 1); CP_COMMIT();

    for (int c = 0; c < NC; c++) {
        CP_WAIT1();
        __syncthreads();
        const int slot = c % 3;
        const __half* sA = (const __half*)(smem + slot * STAGE_B);
        const __half* sB = (const __half*)(smem + slot * STAGE_B + 18432);
#pragma unroll
        for (int kk = 0; kk < 4; kk++) {
            wmma::fragment<wmma::matrix_a, 16, 16, 16, __half,
                           wmma::row_major> a[2];
            wmma::fragment<wmma::matrix_b, 16, 16, 16, __half,
                           wmma::col_major> b[4];
#pragma unroll
            for (int i = 0; i < 2; i++)
                wmma::load_matrix_sync(a[i], sA + (wr * 32 + i * 16) * 72 + kk * 16, 72);
#pragma unroll
            for (int j = 0; j < 4; j++)
                wmma::load_matrix_sync(b[j], sB + (wc * 64 + j * 16) * 72 + kk * 16, 72);
#pragma unroll
            for (int i = 0; i < 2; i++)
#pragma unroll
                for (int j = 0; j < 4; j++)
                    wmma::mma_sync(acc[i][j], a[i], b[j], acc[i][j]);
        }
        __syncthreads();
        const int cn = c + 2;
        if (cn < NC) load_stage(cn % 3, cn);
        CP_COMMIT();
    }

    CP_WAIT0();
    __syncthreads();

    // epilogue: scratch aliases stage smem (mainloop done)
    float* scr = (float*)smem + wid * 16 * 24;
#pragma unroll
    for (int i = 0; i < 2; i++)
#pragma unroll
        for (int j = 0; j < 4; j++) {
            wmma::store_matrix_sync(scr, acc[i][j], 24, wmma::mem_row_major);
            __syncwarp();
            int r  = lane >> 1;
            int ch = (lane & 1) * 8;
            int gr = m0 + wr * 32 + i * 16 + r;
            int gc = n0 + wc * 64 + j * 16 + ch;
            if (gr < M) {
                float4 b0 = *(const float4*)(bias + gc);
                float4 b1 = *(const float4*)(bias + gc + 4);
                float v[8];
                v[0] = scr[r * 24 + ch + 0] + b0.x;
                v[1] = scr[r * 24 + ch + 1] + b0.y;
                v[2] = scr[r * 24 + ch + 2] + b0.z;
                v[3] = scr[r * 24 + ch + 3] + b0.w;
                v[4] = scr[r * 24 + ch + 4] + b1.x;
                v[5] = scr[r * 24 + ch + 5] + b1.y;
                v[6] = scr[r * 24 + ch + 6] + b1.z;
                v[7] = scr[r * 24 + ch + 7] + b1.w;
                if (act) {
#pragma unroll
                    for (int e = 0; e < 8; e++)
                        v[e] = 0.5f * v[e] *
                               (1.0f + erff(v[e] * 0.70710678118654752f));
                }
                if (Cf) {
                    float* cp = Cf + (size_t)gr * N + gc;
                    *(float4*)cp       = make_float4(v[0], v[1], v[2], v[3]);
                    *(float4*)(cp + 4) = make_float4(v[4], v[5], v[6], v[7]);
                }
                if (Ch) {
                    __half* hp = Ch + (size_t)gr * N + gc;
                    write4h(hp,     make_float4(v[0], v[1], v[2], v[3]));
                    write4h(hp + 4, make_float4(v[4], v[5], v[6], v[7]));
                }
            }
            __syncwarp();
        }
}

// ---------------------------------------------------------------------------
// Set attention (fp32 exact); writes fp16 output
// ---------------------------------------------------------------------------
__global__ __launch_bounds__(144, 1) void attn_kernel(
    const float* __restrict__ qkp, const float* __restrict__ vb,
    const void* __restrict__ maskp, int mask_off,
    __half* __restrict__ outb)
{
    const int s   = blockIdx.x;
    const int h0  = blockIdx.y * 4;
    const int tid = threadIdx.x;
    const int hl  = tid / SETSZ;
    const int l   = tid - hl * SETSZ;

    __shared__ float ks[4][SETSZ][DHEAD];
    __shared__ float vs[4][SETSZ][DHEAD];
    __shared__ float msk[SETSZ];

    if (tid < SETSZ) {
        int gi = mask_off + s * SETSZ + tid;
        int mode = g_mask_mode;
        bool m;
        if (mode == 0)      m = ((const int*)maskp)[gi] != 0;
        else if (mode == 1) m = ((const unsigned char*)maskp)[gi] != 0;
        else                m = ((const float*)maskp)[gi] != 0.0f;
        msk[tid] = m ? -INFINITY : 0.0f;
    }
    for (int idx = tid; idx < 4 * SETSZ * DHEAD; idx += 144) {
        int d  = idx & (DHEAD - 1);
        int m  = (idx >> 5) % SETSZ;
        int hh = idx / (DHEAD * SETSZ);
        size_t row = (size_t)s * SETSZ + m;
        ks[hh][m][d] = qkp[row * 512 + 256 + (size_t)(h0 + hh) * DHEAD + d];
        vs[hh][m][d] = vb [row * 256 +       (size_t)(h0 + hh) * DHEAD + d];
    }
    __syncthreads();

    float q[DHEAD];
    {
        const float4* qr = (const float4*)(qkp + ((size_t)s * SETSZ + l) * 512
                                           + (size_t)(h0 + hl) * DHEAD);
#pragma unroll
        for (int d4 = 0; d4 < 8; d4++) {
            float4 vq = qr[d4];
            q[d4*4+0] = vq.x; q[d4*4+1] = vq.y; q[d4*4+2] = vq.z; q[d4*4+3] = vq.w;
        }
    }
    const float scale = 0.17677669529663687f;
    float sc[SETSZ];
    float mx = -INFINITY;
#pragma unroll
    for (int m = 0; m < SETSZ; m++) {
        float a = 0.f;
#pragma unroll
        for (int d = 0; d < DHEAD; d++) a += q[d] * ks[hl][m][d];
        a = a * scale + msk[m];
        sc[m] = a;
        mx = fmaxf(mx, a);
    }
    float den = 0.f;
#pragma unroll
    for (int m = 0; m < SETSZ; m++) { float e = expf(sc[m] - mx); sc[m] = e; den += e; }
    float inv = 1.0f / den;
    float o[DHEAD];
#pragma unroll
    for (int d = 0; d < DHEAD; d++) o[d] = 0.f;
#pragma unroll
    for (int m = 0; m < SETSZ; m++) {
        float a = sc[m] * inv;
#pragma unroll
        for (int d = 0; d < DHEAD; d++) o[d] += a * vs[hl][m][d];
    }
    __half* op = outb + ((size_t)s * SETSZ + l) * 256 + (size_t)(h0 + hl) * DHEAD;
#pragma unroll
    for (int p = 0; p < 8; p++)
        write4h(op + p * 4,
                make_float4(o[p*4], o[p*4+1], o[p*4+2], o[p*4+3]));
}

// ---------------------------------------------------------------------------
// LayerNorm helpers
// ---------------------------------------------------------------------------
__device__ __forceinline__ float wsum(float v)
{
#pragma unroll
    for (int o = 16; o > 0; o >>= 1) v += __shfl_xor_sync(0xffffffffu, v, o);
    return v;
}

__device__ __forceinline__ void ln8(float4& v0, float4& v1,
                                    const float* __restrict__ g,
                                    const float* __restrict__ b, int lane)
{
    float s  = v0.x + v0.y + v0.z + v0.w + v1.x + v1.y + v1.z + v1.w;
    float ss = v0.x*v0.x + v0.y*v0.y + v0.z*v0.z + v0.w*v0.w
             + v1.x*v1.x + v1.y*v1.y + v1.z*v1.z + v1.w*v1.w;
    s = wsum(s); ss = wsum(ss);
    float mean = s * (1.0f / 256.0f);
    float var  = ss * (1.0f / 256.0f) - mean * mean;
    float inv  = rsqrtf(fmaxf(var, 0.0f) + 1e-5f);
    float4 G0 = ((const float4*)g)[lane];
    float4 G1 = ((const float4*)g)[lane + 32];
    float4 B0 = ((const float4*)b)[lane];
    float4 B1 = ((const float4*)b)[lane + 32];
    v0.x = (v0.x - mean) * inv * G0.x + B0.x;
    v0.y = (v0.y - mean) * inv * G0.y + B0.y;
    v0.z = (v0.z - mean) * inv * G0.z + B0.z;
    v0.w = (v0.w - mean) * inv * G0.w + B0.w;
    v1.x = (v1.x - mean) * inv * G1.x + B1.x;
    v1.y = (v1.y - mean) * inv * G1.y + B1.y;
    v1.z = (v1.z - mean) * inv * G1.z + B1.z;
    v1.w = (v1.w - mean) * inv * G1.w + B1.w;
}

__device__ __forceinline__ float4 f4add(float4 a, float4 b)
{ return make_float4(a.x + b.x, a.y + b.y, a.z + b.z, a.w + b.w); }

// x1[t] = LN(x[t] + o[j]), t = inds[j]; fp32 + fp16 copies
__global__ __launch_bounds__(256) void ln1_scatter_kernel(
    const float* __restrict__ x, const float* __restrict__ o,
    const int* __restrict__ inds, const float* __restrict__ g,
    const float* __restrict__ b, float* __restrict__ out,
    __half* __restrict__ outb)
{
    int w = (blockIdx.x << 3) + (threadIdx.x >> 5);
    if (w >= NTOK) return;
    int lane = threadIdx.x & 31;
    int t = inds[w];
    const float4* xr  = (const float4*)(x + (size_t)t * 256);
    const float4* orr = (const float4*)(o + (size_t)w * 256);
    float4 v0 = f4add(xr[lane],      orr[lane]);
    float4 v1 = f4add(xr[lane + 32], orr[lane + 32]);
    ln8(v0, v1, g, b, lane);
    ((float4*)(out + (size_t)t * 256))[lane]      = v0;
    ((float4*)(out + (size_t)t * 256))[lane + 32] = v1;
    __half* ar = outb + (size_t)t * 256;
    write4h(ar + lane * 4,       v0);
    write4h(ar + 128 + lane * 4, v1);
}

__global__ __launch_bounds__(256) void ln2_enc_kernel(
    const float* __restrict__ x1, const float* __restrict__ ff,
    float* __restrict__ xio,
    const float* __restrict__ g2, const float* __restrict__ b2,
    const float* __restrict__ ge, const float* __restrict__ be)
{
    int w = (blockIdx.x << 3) + (threadIdx.x >> 5);
    if (w >= NTOK) return;
    int lane = threadIdx.x & 31;
    const float4* r1 = (const float4*)(x1 + (size_t)w * 256);
    const float4* rf = (const float4*)(ff + (size_t)w * 256);
    float4* rx = (float4*)(xio + (size_t)w * 256);
    float4 v0 = f4add(r1[lane],      rf[lane]);
    float4 v1 = f4add(r1[lane + 32], rf[lane + 32]);
    ln8(v0, v1, g2, b2, lane);
    v0 = f4add(v0, rx[lane]);
    v1 = f4add(v1, rx[lane + 32]);
    ln8(v0, v1, ge, be, lane);
    rx[lane]      = v0;
    rx[lane + 32] = v1;
}

__global__ __launch_bounds__(256) void ln_res_kernel(
    const float* __restrict__ x, const float* __restrict__ r,
    const float* __restrict__ g, const float* __restrict__ b,
    float* __restrict__ out)
{
    int w = (blockIdx.x << 3) + (threadIdx.x >> 5);
    if (w >= NTOK) return;
    int lane = threadIdx.x & 31;
    const float4* xr = (const float4*)(x + (size_t)w * 256);
    const float4* rr = (const float4*)(r + (size_t)w * 256);
    float4 v0 = f4add(xr[lane],      rr[lane]);
    float4 v1 = f4add(xr[lane + 32], rr[lane + 32]);
    ln8(v0, v1, g, b, lane);
    ((float4*)(out + (size_t)w * 256))[lane]      = v0;
    ((float4*)(out + (size_t)w * 256))[lane + 32] = v1;
}

// ---------------------------------------------------------------------------
// Orchestration
// ---------------------------------------------------------------------------
extern "C" void kernel_launch(void* const* d_in, const int* in_sizes, int n_in,
                              void* d_out, int out_size)
{
    const float* src   = (const float*)d_in[0];
    const float* pos   = (const float*)d_in[1];
    const int*   inds  = (const int*)  d_in[2];
    const void*  masks =               d_in[3];
    const float* ipw   = (const float*)d_in[4];
    const float* ipb   = (const float*)d_in[5];
    const float* oww   = (const float*)d_in[6];
    const float* owb   = (const float*)d_in[7];
    const float* l1w   = (const float*)d_in[8];
    const float* l1b   = (const float*)d_in[9];
    const float* l2w   = (const float*)d_in[10];
    const float* l2b   = (const float*)d_in[11];
    const float* n1g   = (const float*)d_in[12];
    const float* n1b   = (const float*)d_in[13];
    const float* n2g   = (const float*)d_in[14];
    const float* n2b   = (const float*)d_in[15];
    const float* encg  = (const float*)d_in[16];
    const float* encb  = (const float*)d_in[17];
    const float* resg  = (const float*)d_in[18];
    const float* resb  = (const float*)d_in[19];
    float* outp = (float*)d_out;

    char* ws;
    cudaGetSymbolAddress((void**)&ws, g_ws);
    float*  x     = (float*)(ws + OFF_X);
    float*  res   = (float*)(ws + OFF_RES);
    float*  qkp   = (float*)(ws + OFF_QKP);
    float*  x1    = (float*)(ws + OFF_QKP);    // alias: qkp dead after attn
    float*  v     = (float*)(ws + OFF_VOF);
    float*  o     = (float*)(ws + OFF_VOF);
    float*  ff    = (float*)(ws + OFF_VOF);
    __half* qkb   = (__half*)(ws + OFF_QKB);
    __half* x1b   = (__half*)(ws + OFF_QKB);   // alias
    __half* featb = (__half*)(ws + OFF_FEB);
    __half* attnb = (__half*)(ws + OFF_FEB);   // alias
    __half* hb    = (__half*)(ws + OFF_HB);
    __half* ipwb  = (__half*)(ws + OFF_WIP);
    __half* owwb  = (__half*)(ws + OFF_WOW);
    __half* l1wb  = (__half*)(ws + OFF_WL1);
    __half* l2wb  = (__half*)(ws + OFF_WL2);

    cudaFuncSetAttribute(gemm_fp16_kernel,
                         cudaFuncAttributeMaxDynamicSharedMemorySize, GSMEM);

    const size_t xbytes = (size_t)NTOK * CDIM * sizeof(float);
    const int gM = (NTOK + 127) / 128;   // 2049

    detect_mask_kernel<<<1, 256>>>((const unsigned int*)masks,
                                   (2 * 2 * NSETS * SETSZ) / 4);
    wconv_kernel<<<(4 * 768 * 256 + 255) / 256, 256>>>(ipw, ipwb, 4 * 768, 256);
    wconv_kernel<<<(4 * 256 * 256 + 255) / 256, 256>>>(oww, owwb, 4 * 256, 256);
    wconv_kernel<<<(4 * 1024 * 256 + 255) / 256, 256>>>(l1w, l1wb, 4 * 1024, 256);
    wconv_kernel<<<(4 * 256 * 1024 + 255) / 256, 256>>>(l2w, l2wb, 4 * 256, 1024);

    cudaMemcpyAsync(x, src, xbytes, cudaMemcpyDeviceToDevice);

    for (int blk = 0; blk < 2; blk++) {
        cudaMemcpyAsync(res, x, xbytes, cudaMemcpyDeviceToDevice);
        for (int i = 0; i < 2; i++) {
            int lid = blk * 2 + i;
            const int* ip = inds + (size_t)lid * NSETS * SETSZ;
            int moff = lid * NSETS * SETSZ;
            const float* pp = pos + (size_t)lid * NTOK * CDIM;

            gather_kernel<<<(NTOK * 64 + 255) / 256, 256>>>(
                x, pp, ip, qkb, featb);

            // in-proj QK (N=512) and V (N=256)
            gemm_fp16_kernel<<<dim3(4, gM), 256, GSMEM>>>(
                qkb, 256, ipwb + (size_t)lid * 768 * 512,
                ipb + (size_t)lid * 768, qkp, nullptr, NTOK, 512, 0);
            gemm_fp16_kernel<<<dim3(2, gM), 256, GSMEM>>>(
                featb, 256, ipwb + (size_t)lid * 768 * 512 + (size_t)512 * 512,
                ipb + (size_t)lid * 768 + 512, v, nullptr, NTOK, 256, 0);

            attn_kernel<<<dim3(NSETS, 2), 144>>>(qkp, v, masks, moff, attnb);

            gemm_fp16_kernel<<<dim3(2, gM), 256, GSMEM>>>(
                attnb, 256, owwb + (size_t)lid * 256 * 512,
                owb + (size_t)lid * 256, o, nullptr, NTOK, 256, 0);

            ln1_scatter_kernel<<<(NTOK + 7) / 8, 256>>>(
                x, o, ip, n1g + (size_t)lid * 256, n1b + (size_t)lid * 256,
                x1, x1b);

            gemm_fp16_kernel<<<dim3(8, gM), 256, GSMEM>>>(
                x1b, 256, l1wb + (size_t)lid * 1024 * 512,
                l1b + (size_t)lid * 1024, nullptr, hb, NTOK, 1024, 1);
            gemm_fp16_kernel<<<dim3(2, gM), 256, GSMEM>>>(
                hb, 1024, l2wb + (size_t)lid * 256 * 2048,
                l2b + (size_t)lid * 256, ff, nullptr, NTOK, 256, 0);

            ln2_enc_kernel<<<(NTOK + 7) / 8, 256>>>(
                x1, ff, x,
                n2g + (size_t)lid * 256, n2b + (size_t)lid * 256,
                encg + (size_t)lid * 256, encb + (size_t)lid * 256);
        }
        float* dst = (blk == 1) ? outp : x;
        ln_res_kernel<<<(NTOK + 7) / 8, 256>>>(
            x, res, resg + (size_t)blk * 256, resb + (size_t)blk * 256, dst);
    }
}

// round 7
// speedup vs baseline: 5.0540x; 1.3539x over previous
#include <cuda_runtime.h>
#include <cuda_fp16.h>
#include <mma.h>
#include <cstdint>
#include <cmath>

using namespace nvcuda;

#define NTOK   262152
#define CDIM   256
#define NSETS  7282
#define SETSZ  36
#define NHEAD  8
#define DHEAD  32
#define DFFN   1024

// ---------------------------------------------------------------------------
// Workspace (single symbol, < 4GB for aarch64 .bss reloc range). ~1.6 GB.
// Aliases (stream-order safe): v==o==ff; x1 in qkp space; x1b==qkb; attnb==featb
// ---------------------------------------------------------------------------
#define SZ_C   ((size_t)NTOK * 256 * 4)
#define SZ_H   ((size_t)NTOK * 256 * 2)
#define OFF_X    ((size_t)0)
#define OFF_RES  (OFF_X   + SZ_C)
#define OFF_QKP  (OFF_RES + SZ_C)          // fp32 NTOK x 512 (x1 aliases)
#define OFF_VOF  (OFF_QKP + 2 * SZ_C)      // v / o / ff
#define OFF_QKB  (OFF_VOF + SZ_C)          // fp16 NTOK x 256 (x1b aliases)
#define OFF_FEB  (OFF_QKB + SZ_H)          // fp16 NTOK x 256 (attnb aliases)
#define OFF_HB   (OFF_FEB + SZ_H)          // fp16 NTOK x 1024
#define OFF_WIP  (OFF_HB  + (size_t)NTOK * 1024 * 2)
#define OFF_WOW  (OFF_WIP + (size_t)4*768*256*2)
#define OFF_WL1  (OFF_WOW + (size_t)4*256*256*2)
#define OFF_WL2  (OFF_WL1 + (size_t)4*1024*256*2)
#define WS_TOT   (OFF_WL2 + (size_t)4*256*1024*2)

__device__ __align__(256) char g_ws[WS_TOT];
__device__ int g_mask_mode;

// ---------------------------------------------------------------------------
// Helpers
// ---------------------------------------------------------------------------
__device__ __forceinline__ uint32_t smem_u32(const void* p) {
    uint32_t a;
    asm("{ .reg .u64 t; cvta.to.shared.u64 t, %1; cvt.u32.u64 %0, t; }"
        : "=r"(a) : "l"(p));
    return a;
}
__device__ __forceinline__ void cp16(uint32_t dst, const void* src, int sz) {
    asm volatile("cp.async.cg.shared.global [%0], [%1], 16, %2;"
                 :: "r"(dst), "l"(src), "r"(sz) : "memory");
}
#define CP_COMMIT() asm volatile("cp.async.commit_group;" ::: "memory")
#define CP_WAIT1()  asm volatile("cp.async.wait_group 1;" ::: "memory")
#define CP_WAIT0()  asm volatile("cp.async.wait_group 0;" ::: "memory")

__device__ __forceinline__ uint32_t pack2h(float a, float b) {
    __half2 h;
    h.x = __float2half_rn(a); h.y = __float2half_rn(b);
    return *reinterpret_cast<uint32_t*>(&h);
}
__device__ __forceinline__ void write4h(__half* p, float4 v) {
    *(uint2*)p = make_uint2(pack2h(v.x, v.y), pack2h(v.z, v.w));
}

// ---------------------------------------------------------------------------
// Weight converter: fp32 -> plain fp16
// ---------------------------------------------------------------------------
__global__ __launch_bounds__(256) void wconv_kernel(
    const float* __restrict__ src, __half* __restrict__ dst, int n)
{
    int idx = blockIdx.x * 256 + threadIdx.x;
    if (idx >= n) return;
    dst[idx] = __float2half_rn(src[idx]);
}

// ---------------------------------------------------------------------------
// Mask dtype detector
// ---------------------------------------------------------------------------
__global__ void detect_mask_kernel(const unsigned int* __restrict__ w, int nwords)
{
    __shared__ int f32f, u8f;
    if (threadIdx.x == 0) { f32f = 0; u8f = 0; }
    __syncthreads();
    int lf = 0, lu = 0;
    for (int i = threadIdx.x; i < nwords; i += blockDim.x) {
        unsigned int x = w[i];
        if (x == 0x3F800000u) lf = 1;
        else if (x > 1u)      lu = 1;
    }
    if (lf) f32f = 1;
    if (lu) u8f = 1;
    __syncthreads();
    if (threadIdx.x == 0) g_mask_mode = f32f ? 2 : (u8f ? 1 : 0);
}

// ---------------------------------------------------------------------------
// Gather: fp16 qk (= x[inds]+pos[inds]) and feat (= x[inds])
// ---------------------------------------------------------------------------
__global__ __launch_bounds__(256) void gather_kernel(
    const float* __restrict__ x, const float* __restrict__ pos,
    const int* __restrict__ inds, __half* __restrict__ qkb,
    __half* __restrict__ featb)
{
    int idx = blockIdx.x * 256 + threadIdx.x;
    if (idx >= NTOK * 64) return;
    int j  = idx >> 6;
    int c4 = idx & 63;
    int t  = inds[j];
    float4 xv = ((const float4*)x)  [(size_t)t * 64 + c4];
    float4 pv = ((const float4*)pos)[(size_t)t * 64 + c4];
    float4 q  = make_float4(xv.x + pv.x, xv.y + pv.y, xv.z + pv.z, xv.w + pv.w);
    write4h(featb + (size_t)j * 256 + c4 * 4, xv);
    write4h(qkb   + (size_t)j * 256 + c4 * 4, q);
}

// ---------------------------------------------------------------------------
// fp16 GEMM: C[m,n] = fp16(A[m,:]) . fp16(W[n,:]) + bias[n] (+GELU), fp32 acc
// CTA 128x128, BK=64, 3-stage cp.async pipeline, 8 warps of m32 x n64.
// ---------------------------------------------------------------------------
#define STAGE_B 36864          // A 128x144B + B 128x144B
#define GSMEM   (3 * STAGE_B)  // 110592; epilogue scratch aliases stage 0

__global__ __launch_bounds__(256, 2) void gemm_fp16_kernel(
    const __half* __restrict__ A, int KA,
    const __half* __restrict__ W, const float* __restrict__ bias,
    float* __restrict__ Cf, __half* __restrict__ Ch,
    int M, int N, int act)
{
    extern __shared__ char smem[];
    const uint32_t sb = smem_u32(smem);
    const int tid  = threadIdx.x;
    const int wid  = tid >> 5;
    const int lane = tid & 31;
    const int wr   = wid >> 1;   // 0..3
    const int wc   = wid & 1;    // 0..1
    const int m0   = blockIdx.y * 128;
    const int n0   = blockIdx.x * 128;
    const int NC   = KA >> 6;    // BK=64 chunks

    wmma::fragment<wmma::accumulator, 16, 16, 16, float> acc[2][4];
#pragma unroll
    for (int i = 0; i < 2; i++)
#pragma unroll
        for (int j = 0; j < 4; j++) wmma::fill_fragment(acc[i][j], 0.0f);

    // Fill one stage: 128 rows x 128B for A and W (8 x 16B chunks per row).
    auto load_stage = [&](int slot, int c) {
        const int k0 = c << 6;
        const uint32_t base = sb + slot * STAGE_B;
#pragma unroll
        for (int it = 0; it < 4; it++) {
            int i  = tid + it * 256;      // 0..1023
            int r  = i >> 3;              // row 0..127
            int ch = i & 7;               // 16B chunk 0..7
            int gr = m0 + r;
            const __half* sa =
                A + (size_t)(gr < M ? gr : M - 1) * KA + k0 + ch * 8;
            cp16(base + r * 144 + ch * 16, sa, gr < M ? 16 : 0);
            const __half* sw = W + (size_t)(n0 + r) * KA + k0 + ch * 8;
            cp16(base + 18432 + r * 144 + ch * 16, sw, 16);
        }
    };

    load_stage(0, 0); CP_COMMIT();
    load_stage(1, 1); CP_COMMIT();

    for (int c = 0; c < NC; c++) {
        CP_WAIT1();
        __syncthreads();
        const int slot = c % 3;
        const __half* sA = (const __half*)(smem + slot * STAGE_B);
        const __half* sB = (const __half*)(smem + slot * STAGE_B + 18432);
#pragma unroll
        for (int kk = 0; kk < 4; kk++) {
            wmma::fragment<wmma::matrix_a, 16, 16, 16, __half,
                           wmma::row_major> a[2];
            wmma::fragment<wmma::matrix_b, 16, 16, 16, __half,
                           wmma::col_major> b[4];
#pragma unroll
            for (int i = 0; i < 2; i++)
                wmma::load_matrix_sync(a[i], sA + (wr * 32 + i * 16) * 72 + kk * 16, 72);
#pragma unroll
            for (int j = 0; j < 4; j++)
                wmma::load_matrix_sync(b[j], sB + (wc * 64 + j * 16) * 72 + kk * 16, 72);
#pragma unroll
            for (int i = 0; i < 2; i++)
#pragma unroll
                for (int j = 0; j < 4; j++)
                    wmma::mma_sync(acc[i][j], a[i], b[j], acc[i][j]);
        }
        __syncthreads();
        const int cn = c + 2;
        if (cn < NC) load_stage(cn % 3, cn);
        CP_COMMIT();
    }

    CP_WAIT0();
    __syncthreads();

    // epilogue: scratch aliases stage smem (mainloop done)
    float* scr = (float*)smem + wid * 16 * 24;
#pragma unroll
    for (int i = 0; i < 2; i++)
#pragma unroll
        for (int j = 0; j < 4; j++) {
            wmma::store_matrix_sync(scr, acc[i][j], 24, wmma::mem_row_major);
            __syncwarp();
            int r  = lane >> 1;
            int ch = (lane & 1) * 8;
            int gr = m0 + wr * 32 + i * 16 + r;
            int gc = n0 + wc * 64 + j * 16 + ch;
            if (gr < M) {
                float4 b0 = *(const float4*)(bias + gc);
                float4 b1 = *(const float4*)(bias + gc + 4);
                float v[8];
                v[0] = scr[r * 24 + ch + 0] + b0.x;
                v[1] = scr[r * 24 + ch + 1] + b0.y;
                v[2] = scr[r * 24 + ch + 2] + b0.z;
                v[3] = scr[r * 24 + ch + 3] + b0.w;
                v[4] = scr[r * 24 + ch + 4] + b1.x;
                v[5] = scr[r * 24 + ch + 5] + b1.y;
                v[6] = scr[r * 24 + ch + 6] + b1.z;
                v[7] = scr[r * 24 + ch + 7] + b1.w;
                if (act) {
#pragma unroll
                    for (int e = 0; e < 8; e++)
                        v[e] = 0.5f * v[e] *
                               (1.0f + erff(v[e] * 0.70710678118654752f));
                }
                if (Cf) {
                    float* cp = Cf + (size_t)gr * N + gc;
                    *(float4*)cp       = make_float4(v[0], v[1], v[2], v[3]);
                    *(float4*)(cp + 4) = make_float4(v[4], v[5], v[6], v[7]);
                }
                if (Ch) {
                    __half* hp = Ch + (size_t)gr * N + gc;
                    write4h(hp,     make_float4(v[0], v[1], v[2], v[3]));
                    write4h(hp + 4, make_float4(v[4], v[5], v[6], v[7]));
                }
            }
            __syncwarp();
        }
}

// ---------------------------------------------------------------------------
// Set attention (fp32 exact); writes fp16 output
// ---------------------------------------------------------------------------
__global__ __launch_bounds__(144, 1) void attn_kernel(
    const float* __restrict__ qkp, const float* __restrict__ vb,
    const void* __restrict__ maskp, int mask_off,
    __half* __restrict__ outb)
{
    const int s   = blockIdx.x;
    const int h0  = blockIdx.y * 4;
    const int tid = threadIdx.x;
    const int hl  = tid / SETSZ;
    const int l   = tid - hl * SETSZ;

    __shared__ float ks[4][SETSZ][DHEAD];
    __shared__ float vs[4][SETSZ][DHEAD];
    __shared__ float msk[SETSZ];

    if (tid < SETSZ) {
        int gi = mask_off + s * SETSZ + tid;
        int mode = g_mask_mode;
        bool m;
        if (mode == 0)      m = ((const int*)maskp)[gi] != 0;
        else if (mode == 1) m = ((const unsigned char*)maskp)[gi] != 0;
        else                m = ((const float*)maskp)[gi] != 0.0f;
        msk[tid] = m ? -INFINITY : 0.0f;
    }
    for (int idx = tid; idx < 4 * SETSZ * DHEAD; idx += 144) {
        int d  = idx & (DHEAD - 1);
        int m  = (idx >> 5) % SETSZ;
        int hh = idx / (DHEAD * SETSZ);
        size_t row = (size_t)s * SETSZ + m;
        ks[hh][m][d] = qkp[row * 512 + 256 + (size_t)(h0 + hh) * DHEAD + d];
        vs[hh][m][d] = vb [row * 256 +       (size_t)(h0 + hh) * DHEAD + d];
    }
    __syncthreads();

    float q[DHEAD];
    {
        const float4* qr = (const float4*)(qkp + ((size_t)s * SETSZ + l) * 512
                                           + (size_t)(h0 + hl) * DHEAD);
#pragma unroll
        for (int d4 = 0; d4 < 8; d4++) {
            float4 vq = qr[d4];
            q[d4*4+0] = vq.x; q[d4*4+1] = vq.y; q[d4*4+2] = vq.z; q[d4*4+3] = vq.w;
        }
    }
    const float scale = 0.17677669529663687f;
    float sc[SETSZ];
    float mx = -INFINITY;
#pragma unroll
    for (int m = 0; m < SETSZ; m++) {
        float a = 0.f;
#pragma unroll
        for (int d = 0; d < DHEAD; d++) a += q[d] * ks[hl][m][d];
        a = a * scale + msk[m];
        sc[m] = a;
        mx = fmaxf(mx, a);
    }
    float den = 0.f;
#pragma unroll
    for (int m = 0; m < SETSZ; m++) { float e = expf(sc[m] - mx); sc[m] = e; den += e; }
    float inv = 1.0f / den;
    float o[DHEAD];
#pragma unroll
    for (int d = 0; d < DHEAD; d++) o[d] = 0.f;
#pragma unroll
    for (int m = 0; m < SETSZ; m++) {
        float a = sc[m] * inv;
#pragma unroll
        for (int d = 0; d < DHEAD; d++) o[d] += a * vs[hl][m][d];
    }
    __half* op = outb + ((size_t)s * SETSZ + l) * 256 + (size_t)(h0 + hl) * DHEAD;
#pragma unroll
    for (int p = 0; p < 8; p++)
        write4h(op + p * 4,
                make_float4(o[p*4], o[p*4+1], o[p*4+2], o[p*4+3]));
}

// ---------------------------------------------------------------------------
// LayerNorm helpers
// ---------------------------------------------------------------------------
__device__ __forceinline__ float wsum(float v)
{
#pragma unroll
    for (int o = 16; o > 0; o >>= 1) v += __shfl_xor_sync(0xffffffffu, v, o);
    return v;
}

__device__ __forceinline__ void ln8(float4& v0, float4& v1,
                                    const float* __restrict__ g,
                                    const float* __restrict__ b, int lane)
{
    float s  = v0.x + v0.y + v0.z + v0.w + v1.x + v1.y + v1.z + v1.w;
    float ss = v0.x*v0.x + v0.y*v0.y + v0.z*v0.z + v0.w*v0.w
             + v1.x*v1.x + v1.y*v1.y + v1.z*v1.z + v1.w*v1.w;
    s = wsum(s); ss = wsum(ss);
    float mean = s * (1.0f / 256.0f);
    float var  = ss * (1.0f / 256.0f) - mean * mean;
    float inv  = rsqrtf(fmaxf(var, 0.0f) + 1e-5f);
    float4 G0 = ((const float4*)g)[lane];
    float4 G1 = ((const float4*)g)[lane + 32];
    float4 B0 = ((const float4*)b)[lane];
    float4 B1 = ((const float4*)b)[lane + 32];
    v0.x = (v0.x - mean) * inv * G0.x + B0.x;
    v0.y = (v0.y - mean) * inv * G0.y + B0.y;
    v0.z = (v0.z - mean) * inv * G0.z + B0.z;
    v0.w = (v0.w - mean) * inv * G0.w + B0.w;
    v1.x = (v1.x - mean) * inv * G1.x + B1.x;
    v1.y = (v1.y - mean) * inv * G1.y + B1.y;
    v1.z = (v1.z - mean) * inv * G1.z + B1.z;
    v1.w = (v1.w - mean) * inv * G1.w + B1.w;
}

__device__ __forceinline__ float4 f4add(float4 a, float4 b)
{ return make_float4(a.x + b.x, a.y + b.y, a.z + b.z, a.w + b.w); }

// x1[t] = LN(x[t] + o[j]), t = inds[j]; fp32 + fp16 copies
__global__ __launch_bounds__(256) void ln1_scatter_kernel(
    const float* __restrict__ x, const float* __restrict__ o,
    const int* __restrict__ inds, const float* __restrict__ g,
    const float* __restrict__ b, float* __restrict__ out,
    __half* __restrict__ outb)
{
    int w = (blockIdx.x << 3) + (threadIdx.x >> 5);
    if (w >= NTOK) return;
    int lane = threadIdx.x & 31;
    int t = inds[w];
    const float4* xr  = (const float4*)(x + (size_t)t * 256);
    const float4* orr = (const float4*)(o + (size_t)w * 256);
    float4 v0 = f4add(xr[lane],      orr[lane]);
    float4 v1 = f4add(xr[lane + 32], orr[lane + 32]);
    ln8(v0, v1, g, b, lane);
    ((float4*)(out + (size_t)t * 256))[lane]      = v0;
    ((float4*)(out + (size_t)t * 256))[lane + 32] = v1;
    __half* ar = outb + (size_t)t * 256;
    write4h(ar + lane * 4,       v0);
    write4h(ar + 128 + lane * 4, v1);
}

__global__ __launch_bounds__(256) void ln2_enc_kernel(
    const float* __restrict__ x1, const float* __restrict__ ff,
    float* __restrict__ xio,
    const float* __restrict__ g2, const float* __restrict__ b2,
    const float* __restrict__ ge, const float* __restrict__ be)
{
    int w = (blockIdx.x << 3) + (threadIdx.x >> 5);
    if (w >= NTOK) return;
    int lane = threadIdx.x & 31;
    const float4* r1 = (const float4*)(x1 + (size_t)w * 256);
    const float4* rf = (const float4*)(ff + (size_t)w * 256);
    float4* rx = (float4*)(xio + (size_t)w * 256);
    float4 v0 = f4add(r1[lane],      rf[lane]);
    float4 v1 = f4add(r1[lane + 32], rf[lane + 32]);
    ln8(v0, v1, g2, b2, lane);
    v0 = f4add(v0, rx[lane]);
    v1 = f4add(v1, rx[lane + 32]);
    ln8(v0, v1, ge, be, lane);
    rx[lane]      = v0;
    rx[lane + 32] = v1;
}

__global__ __launch_bounds__(256) void ln_res_kernel(
    const float* __restrict__ x, const float* __restrict__ r,
    const float* __restrict__ g, const float* __restrict__ b,
    float* __restrict__ out)
{
    int w = (blockIdx.x << 3) + (threadIdx.x >> 5);
    if (w >= NTOK) return;
    int lane = threadIdx.x & 31;
    const float4* xr = (const float4*)(x + (size_t)w * 256);
    const float4* rr = (const float4*)(r + (size_t)w * 256);
    float4 v0 = f4add(xr[lane],      rr[lane]);
    float4 v1 = f4add(xr[lane + 32], rr[lane + 32]);
    ln8(v0, v1, g, b, lane);
    ((float4*)(out + (size_t)w * 256))[lane]      = v0;
    ((float4*)(out + (size_t)w * 256))[lane + 32] = v1;
}

// ---------------------------------------------------------------------------
// Orchestration
// ---------------------------------------------------------------------------
extern "C" void kernel_launch(void* const* d_in, const int* in_sizes, int n_in,
                              void* d_out, int out_size)
{
    const float* src   = (const float*)d_in[0];
    const float* pos   = (const float*)d_in[1];
    const int*   inds  = (const int*)  d_in[2];
    const void*  masks =               d_in[3];
    const float* ipw   = (const float*)d_in[4];
    const float* ipb   = (const float*)d_in[5];
    const float* oww   = (const float*)d_in[6];
    const float* owb   = (const float*)d_in[7];
    const float* l1w   = (const float*)d_in[8];
    const float* l1b   = (const float*)d_in[9];
    const float* l2w   = (const float*)d_in[10];
    const float* l2b   = (const float*)d_in[11];
    const float* n1g   = (const float*)d_in[12];
    const float* n1b   = (const float*)d_in[13];
    const float* n2g   = (const float*)d_in[14];
    const float* n2b   = (const float*)d_in[15];
    const float* encg  = (const float*)d_in[16];
    const float* encb  = (const float*)d_in[17];
    const float* resg  = (const float*)d_in[18];
    const float* resb  = (const float*)d_in[19];
    float* outp = (float*)d_out;

    char* ws;
    cudaGetSymbolAddress((void**)&ws, g_ws);
    float*  x     = (float*)(ws + OFF_X);
    float*  res   = (float*)(ws + OFF_RES);
    float*  qkp   = (float*)(ws + OFF_QKP);
    float*  x1    = (float*)(ws + OFF_QKP);    // alias: qkp dead after attn
    float*  v     = (float*)(ws + OFF_VOF);
    float*  o     = (float*)(ws + OFF_VOF);
    float*  ff    = (float*)(ws + OFF_VOF);
    __half* qkb   = (__half*)(ws + OFF_QKB);
    __half* x1b   = (__half*)(ws + OFF_QKB);   // alias
    __half* featb = (__half*)(ws + OFF_FEB);
    __half* attnb = (__half*)(ws + OFF_FEB);   // alias
    __half* hb    = (__half*)(ws + OFF_HB);
    __half* ipwb  = (__half*)(ws + OFF_WIP);
    __half* owwb  = (__half*)(ws + OFF_WOW);
    __half* l1wb  = (__half*)(ws + OFF_WL1);
    __half* l2wb  = (__half*)(ws + OFF_WL2);

    cudaFuncSetAttribute(gemm_fp16_kernel,
                         cudaFuncAttributeMaxDynamicSharedMemorySize, GSMEM);

    const size_t xbytes = (size_t)NTOK * CDIM * sizeof(float);
    const int gM = (NTOK + 127) / 128;   // 2049

    detect_mask_kernel<<<1, 256>>>((const unsigned int*)masks,
                                   (2 * 2 * NSETS * SETSZ) / 4);
    wconv_kernel<<<(4 * 768 * 256 + 255) / 256, 256>>>(ipw, ipwb, 4 * 768 * 256);
    wconv_kernel<<<(4 * 256 * 256 + 255) / 256, 256>>>(oww, owwb, 4 * 256 * 256);
    wconv_kernel<<<(4 * 1024 * 256 + 255) / 256, 256>>>(l1w, l1wb, 4 * 1024 * 256);
    wconv_kernel<<<(4 * 256 * 1024 + 255) / 256, 256>>>(l2w, l2wb, 4 * 256 * 1024);

    cudaMemcpyAsync(x, src, xbytes, cudaMemcpyDeviceToDevice);

    for (int blk = 0; blk < 2; blk++) {
        cudaMemcpyAsync(res, x, xbytes, cudaMemcpyDeviceToDevice);
        for (int i = 0; i < 2; i++) {
            int lid = blk * 2 + i;
            const int* ip = inds + (size_t)lid * NSETS * SETSZ;
            int moff = lid * NSETS * SETSZ;
            const float* pp = pos + (size_t)lid * NTOK * CDIM;

            gather_kernel<<<(NTOK * 64 + 255) / 256, 256>>>(
                x, pp, ip, qkb, featb);

            // in-proj QK (N=512) and V (N=256)
            gemm_fp16_kernel<<<dim3(4, gM), 256, GSMEM>>>(
                qkb, 256, ipwb + (size_t)lid * 768 * 256,
                ipb + (size_t)lid * 768, qkp, nullptr, NTOK, 512, 0);
            gemm_fp16_kernel<<<dim3(2, gM), 256, GSMEM>>>(
                featb, 256, ipwb + (size_t)lid * 768 * 256 + (size_t)512 * 256,
                ipb + (size_t)lid * 768 + 512, v, nullptr, NTOK, 256, 0);

            attn_kernel<<<dim3(NSETS, 2), 144>>>(qkp, v, masks, moff, attnb);

            gemm_fp16_kernel<<<dim3(2, gM), 256, GSMEM>>>(
                attnb, 256, owwb + (size_t)lid * 256 * 256,
                owb + (size_t)lid * 256, o, nullptr, NTOK, 256, 0);

            ln1_scatter_kernel<<<(NTOK + 7) / 8, 256>>>(
                x, o, ip, n1g + (size_t)lid * 256, n1b + (size_t)lid * 256,
                x1, x1b);

            gemm_fp16_kernel<<<dim3(8, gM), 256, GSMEM>>>(
                x1b, 256, l1wb + (size_t)lid * 1024 * 256,
                l1b + (size_t)lid * 1024, nullptr, hb, NTOK, 1024, 1);
            gemm_fp16_kernel<<<dim3(2, gM), 256, GSMEM>>>(
                hb, 1024, l2wb + (size_t)lid * 256 * 1024,
                l2b + (size_t)lid * 256, ff, nullptr, NTOK, 256, 0);

            ln2_enc_kernel<<<(NTOK + 7) / 8, 256>>>(
                x1, ff, x,
                n2g + (size_t)lid * 256, n2b + (size_t)lid * 256,
                encg + (size_t)lid * 256, encb + (size_t)lid * 256);
        }
        float* dst = (blk == 1) ? outp : x;
        ln_res_kernel<<<(NTOK + 7) / 8, 256>>>(
            x, res, resg + (size_t)blk * 256, resb + (size_t)blk * 256, dst);
    }
}